// round 2
// baseline (speedup 1.0000x reference)
#include <cuda_runtime.h>
#include <math.h>

#define TT   512
#define HH   64
#define DD   576
#define DV   512
#define TOPK 1024
#define TILE 32
#define NTILES (TOPK / TILE)   // 32
#define HG   16                // heads per block
#define NHG  (HH / HG)         // 4
#define KV_STRIDE 577          // odd stride -> conflict-free banks

// dynamic smem layout (floats):
//   sKV  [32*577]
//   sS   [16*33]
//   sP   [16*33]
//   sC   [16]
//   sM   [16]
//   sL   [16]
//   sIdx [32] (int)
#define SMEM_FLOATS (TILE*KV_STRIDE + 2*HG*33 + 3*HG)
#define SMEM_BYTES  (SMEM_FLOATS*4 + TILE*4)

__global__ void __launch_bounds__(256, 1)
mla_sparse_attn_kernel(const float* __restrict__ q,     // [T,H,D]
                       const float* __restrict__ kv,    // [NKV,D]
                       const int*   __restrict__ topk,  // [T,TOPK]
                       const float* __restrict__ sink,  // [H]
                       float*       __restrict__ out)   // [T,H,DV]
{
    extern __shared__ float smem[];
    float* sKV = smem;                       // [32][577]
    float* sS  = sKV + TILE * KV_STRIDE;     // [16][33]
    float* sP  = sS + HG * 33;               // [16][33]
    float* sC  = sP + HG * 33;               // [16]
    float* sM  = sC + HG;                    // [16]
    float* sL  = sM + HG;                    // [16]
    int*   sIdx = (int*)(sL + HG);           // [32]

    const int hg   = blockIdx.x;             // 0..3
    const int t    = blockIdx.y;             // 0..511
    const int tid  = threadIdx.x;
    const int lane = tid & 31;
    const int w    = tid >> 5;               // warp 0..7

    const float scale = 1.0f / 24.0f;        // 1/sqrt(576)

    if (tid < HG) { sM[tid] = -INFINITY; sL[tid] = 0.0f; }

    // ---- score-phase assignment: warp covers 4 heads x 16 kv-rows ----
    const int s_hbase = (w & 3) * 4;         // local head base (0,4,8,12)
    const int s_kbase = (w >> 2) * 16;       // kv half (0 or 16)

    // q for 4 heads in registers, element d = lane + 32*i
    float qreg[4][18];
    #pragma unroll
    for (int j = 0; j < 4; ++j) {
        const float* qp = q + ((size_t)t * HH + (size_t)hg * HG + s_hbase + j) * DD + lane;
        #pragma unroll
        for (int i = 0; i < 18; ++i) qreg[j][i] = qp[i * 32];
    }

    // ---- PV-phase assignment: warp covers 2 heads, lane owns v-dims lane+32*i ----
    const int p_h0 = w * 2;                  // local heads p_h0, p_h0+1
    float acc0[16], acc1[16];
    #pragma unroll
    for (int i = 0; i < 16; ++i) { acc0[i] = 0.0f; acc1[i] = 0.0f; }

    const int* tkp = topk + (size_t)t * TOPK;

    for (int kt = 0; kt < NTILES; ++kt) {
        // 1) load tile indices
        if (tid < TILE) sIdx[tid] = tkp[kt * TILE + tid];
        __syncthreads();   // also guarantees previous PV finished reading sKV

        // 2) gather: lane = row, warp = 72-float segment (contiguous 288B per thread)
        {
            int idxv = sIdx[lane];
            int row  = idxv < 0 ? 0 : idxv;
            const float4* src = (const float4*)(kv + (size_t)row * DD) + w * 18;
            float* dst = sKV + lane * KV_STRIDE + w * 72;
            #pragma unroll
            for (int i = 0; i < 18; ++i) {
                float4 v = src[i];
                dst[i * 4 + 0] = v.x;
                dst[i * 4 + 1] = v.y;
                dst[i * 4 + 2] = v.z;
                dst[i * 4 + 3] = v.w;
            }
        }
        __syncthreads();

        // 3) scores: 4 heads x 16 k per warp, butterfly reduce over lanes
        #pragma unroll 1
        for (int kk = 0; kk < 16; ++kk) {
            const int k = s_kbase + kk;
            const float* kvp = sKV + k * KV_STRIDE + lane;
            float s0 = 0.f, s1 = 0.f, s2 = 0.f, s3 = 0.f;
            #pragma unroll
            for (int i = 0; i < 18; ++i) {
                float v = kvp[i * 32];
                s0 += qreg[0][i] * v;
                s1 += qreg[1][i] * v;
                s2 += qreg[2][i] * v;
                s3 += qreg[3][i] * v;
            }
            #pragma unroll
            for (int off = 16; off; off >>= 1) {
                s0 += __shfl_xor_sync(0xFFFFFFFFu, s0, off);
                s1 += __shfl_xor_sync(0xFFFFFFFFu, s1, off);
                s2 += __shfl_xor_sync(0xFFFFFFFFu, s2, off);
                s3 += __shfl_xor_sync(0xFFFFFFFFu, s3, off);
            }
            if (lane == 0) {
                bool valid = sIdx[k] >= 0;
                sS[(s_hbase + 0) * 33 + k] = valid ? s0 * scale : -INFINITY;
                sS[(s_hbase + 1) * 33 + k] = valid ? s1 * scale : -INFINITY;
                sS[(s_hbase + 2) * 33 + k] = valid ? s2 * scale : -INFINITY;
                sS[(s_hbase + 3) * 33 + k] = valid ? s3 * scale : -INFINITY;
            }
        }
        __syncthreads();

        // 4) online softmax (one thread per head)
        if (tid < HG) {
            const int h = tid;
            float m_old = sM[h];
            float tmax = -INFINITY;
            #pragma unroll
            for (int k = 0; k < TILE; ++k) tmax = fmaxf(tmax, sS[h * 33 + k]);
            float m_new = fmaxf(m_old, tmax);
            float c, l = sL[h];
            if (m_new == -INFINITY) {
                c = 1.0f;
                #pragma unroll
                for (int k = 0; k < TILE; ++k) sP[h * 33 + k] = 0.0f;
            } else {
                c = __expf(m_old - m_new);   // exp(-inf) = 0 on first tile
                float ls = 0.0f;
                #pragma unroll
                for (int k = 0; k < TILE; ++k) {
                    float p = __expf(sS[h * 33 + k] - m_new);
                    sP[h * 33 + k] = p;
                    ls += p;
                }
                l = l * c + ls;
            }
            sC[h] = c; sM[h] = m_new; sL[h] = l;
        }
        __syncthreads();

        // 5) PV rank-32 update: warp handles 2 heads, lane owns d = lane+32*i
        {
            float c0 = sC[p_h0], c1 = sC[p_h0 + 1];
            #pragma unroll
            for (int i = 0; i < 16; ++i) { acc0[i] *= c0; acc1[i] *= c1; }
            #pragma unroll 1
            for (int k = 0; k < TILE; ++k) {
                float p0 = sP[p_h0 * 33 + k];
                float p1 = sP[(p_h0 + 1) * 33 + k];
                const float* vp = sKV + k * KV_STRIDE + lane;
                #pragma unroll
                for (int i = 0; i < 16; ++i) {
                    float v = vp[i * 32];
                    acc0[i] += p0 * v;
                    acc1[i] += p1 * v;
                }
            }
        }
        // next-iteration top-of-loop barrier protects sKV before regather
    }

    // epilogue: fold in the sink logit exactly as the reference does
    {
        const int hglob0 = hg * HG + p_h0;
        const int hglob1 = hglob0 + 1;

        float m0 = sM[p_h0],     l0 = sL[p_h0],     sk0 = sink[hglob0];
        float m1 = sM[p_h0 + 1], l1 = sL[p_h0 + 1], sk1 = sink[hglob1];

        float mf0 = fmaxf(m0, sk0);
        float f0  = __expf(m0 - mf0);
        float den0 = l0 * f0 + __expf(sk0 - mf0);
        float r0  = f0 / den0;

        float mf1 = fmaxf(m1, sk1);
        float f1  = __expf(m1 - mf1);
        float den1 = l1 * f1 + __expf(sk1 - mf1);
        float r1  = f1 / den1;

        float* op0 = out + ((size_t)t * HH + hglob0) * DV + lane;
        float* op1 = out + ((size_t)t * HH + hglob1) * DV + lane;
        #pragma unroll
        for (int i = 0; i < 16; ++i) {
            op0[i * 32] = acc0[i] * r0;
            op1[i * 32] = acc1[i] * r1;
        }
    }
}

extern "C" void kernel_launch(void* const* d_in, const int* in_sizes, int n_in,
                              void* d_out, int out_size)
{
    const float* q    = (const float*)d_in[0];
    const float* kv   = (const float*)d_in[1];
    const int*   topk = (const int*)d_in[2];
    const float* sink = (const float*)d_in[3];
    float*       out  = (float*)d_out;

    cudaFuncSetAttribute(mla_sparse_attn_kernel,
                         cudaFuncAttributeMaxDynamicSharedMemorySize, SMEM_BYTES);

    dim3 grid(NHG, TT);
    dim3 block(256);
    mla_sparse_attn_kernel<<<grid, block, SMEM_BYTES>>>(q, kv, topk, sink, out);
}

// round 3
// speedup vs baseline: 1.0005x; 1.0005x over previous
#include <cuda_runtime.h>
#include <math.h>

#define TT   512
#define HH   64
#define DD   576
#define DV   512
#define TOPK 1024
#define TILE 32
#define NTILES (TOPK / TILE)   // 32
#define HG   16                // heads per block
#define NHG  (HH / HG)         // 4
#define KV_STRIDE 577          // odd stride -> conflict-free banks

// dynamic smem layout (floats):
//   sKV  [32*577]
//   sS   [16*33]
//   sP   [16*33]
//   sC   [16]
//   sM   [16]
//   sL   [16]
//   sIdx [32] (int)
#define SMEM_FLOATS (TILE*KV_STRIDE + 2*HG*33 + 3*HG)
#define SMEM_BYTES  (SMEM_FLOATS*4 + TILE*4)

__global__ void __launch_bounds__(256, 1)
mla_sparse_attn_kernel(const float* __restrict__ q,     // [T,H,D]
                       const float* __restrict__ kv,    // [NKV,D]
                       const int*   __restrict__ topk,  // [T,TOPK]
                       const float* __restrict__ sink,  // [H]
                       float*       __restrict__ out)   // [T,H,DV]
{
    extern __shared__ float smem[];
    float* sKV = smem;                       // [32][577]
    float* sS  = sKV + TILE * KV_STRIDE;     // [16][33]
    float* sP  = sS + HG * 33;               // [16][33]
    float* sC  = sP + HG * 33;               // [16]
    float* sM  = sC + HG;                    // [16]
    float* sL  = sM + HG;                    // [16]
    int*   sIdx = (int*)(sL + HG);           // [32]

    const int hg   = blockIdx.x;             // 0..3
    const int t    = blockIdx.y;             // 0..511
    const int tid  = threadIdx.x;
    const int lane = tid & 31;
    const int w    = tid >> 5;               // warp 0..7

    const float scale = 1.0f / 24.0f;        // 1/sqrt(576)

    if (tid < HG) { sM[tid] = -INFINITY; sL[tid] = 0.0f; }

    // ---- score-phase assignment: warp covers 4 heads x 16 kv-rows ----
    const int s_hbase = (w & 3) * 4;         // local head base (0,4,8,12)
    const int s_kbase = (w >> 2) * 16;       // kv half (0 or 16)

    // q for 4 heads in registers, element d = lane + 32*i
    float qreg[4][18];
    #pragma unroll
    for (int j = 0; j < 4; ++j) {
        const float* qp = q + ((size_t)t * HH + (size_t)hg * HG + s_hbase + j) * DD + lane;
        #pragma unroll
        for (int i = 0; i < 18; ++i) qreg[j][i] = qp[i * 32];
    }

    // ---- PV-phase assignment: warp covers 2 heads, lane owns v-dims lane+32*i ----
    const int p_h0 = w * 2;                  // local heads p_h0, p_h0+1
    float acc0[16], acc1[16];
    #pragma unroll
    for (int i = 0; i < 16; ++i) { acc0[i] = 0.0f; acc1[i] = 0.0f; }

    const int* tkp = topk + (size_t)t * TOPK;

    for (int kt = 0; kt < NTILES; ++kt) {
        // 1) load tile indices
        if (tid < TILE) sIdx[tid] = tkp[kt * TILE + tid];
        __syncthreads();   // also guarantees previous PV finished reading sKV

        // 2) gather: lane = row, warp = 72-float segment (contiguous 288B per thread)
        {
            int idxv = sIdx[lane];
            int row  = idxv < 0 ? 0 : idxv;
            const float4* src = (const float4*)(kv + (size_t)row * DD) + w * 18;
            float* dst = sKV + lane * KV_STRIDE + w * 72;
            #pragma unroll
            for (int i = 0; i < 18; ++i) {
                float4 v = src[i];
                dst[i * 4 + 0] = v.x;
                dst[i * 4 + 1] = v.y;
                dst[i * 4 + 2] = v.z;
                dst[i * 4 + 3] = v.w;
            }
        }
        __syncthreads();

        // 3) scores: 4 heads x 16 k per warp, butterfly reduce over lanes
        #pragma unroll 1
        for (int kk = 0; kk < 16; ++kk) {
            const int k = s_kbase + kk;
            const float* kvp = sKV + k * KV_STRIDE + lane;
            float s0 = 0.f, s1 = 0.f, s2 = 0.f, s3 = 0.f;
            #pragma unroll
            for (int i = 0; i < 18; ++i) {
                float v = kvp[i * 32];
                s0 += qreg[0][i] * v;
                s1 += qreg[1][i] * v;
                s2 += qreg[2][i] * v;
                s3 += qreg[3][i] * v;
            }
            #pragma unroll
            for (int off = 16; off; off >>= 1) {
                s0 += __shfl_xor_sync(0xFFFFFFFFu, s0, off);
                s1 += __shfl_xor_sync(0xFFFFFFFFu, s1, off);
                s2 += __shfl_xor_sync(0xFFFFFFFFu, s2, off);
                s3 += __shfl_xor_sync(0xFFFFFFFFu, s3, off);
            }
            if (lane == 0) {
                bool valid = sIdx[k] >= 0;
                sS[(s_hbase + 0) * 33 + k] = valid ? s0 * scale : -INFINITY;
                sS[(s_hbase + 1) * 33 + k] = valid ? s1 * scale : -INFINITY;
                sS[(s_hbase + 2) * 33 + k] = valid ? s2 * scale : -INFINITY;
                sS[(s_hbase + 3) * 33 + k] = valid ? s3 * scale : -INFINITY;
            }
        }
        __syncthreads();

        // 4) online softmax (one thread per head)
        if (tid < HG) {
            const int h = tid;
            float m_old = sM[h];
            float tmax = -INFINITY;
            #pragma unroll
            for (int k = 0; k < TILE; ++k) tmax = fmaxf(tmax, sS[h * 33 + k]);
            float m_new = fmaxf(m_old, tmax);
            float c, l = sL[h];
            if (m_new == -INFINITY) {
                c = 1.0f;
                #pragma unroll
                for (int k = 0; k < TILE; ++k) sP[h * 33 + k] = 0.0f;
            } else {
                c = __expf(m_old - m_new);   // exp(-inf) = 0 on first tile
                float ls = 0.0f;
                #pragma unroll
                for (int k = 0; k < TILE; ++k) {
                    float p = __expf(sS[h * 33 + k] - m_new);
                    sP[h * 33 + k] = p;
                    ls += p;
                }
                l = l * c + ls;
            }
            sC[h] = c; sM[h] = m_new; sL[h] = l;
        }
        __syncthreads();

        // 5) PV rank-32 update: warp handles 2 heads, lane owns d = lane+32*i
        {
            float c0 = sC[p_h0], c1 = sC[p_h0 + 1];
            #pragma unroll
            for (int i = 0; i < 16; ++i) { acc0[i] *= c0; acc1[i] *= c1; }
            #pragma unroll 1
            for (int k = 0; k < TILE; ++k) {
                float p0 = sP[p_h0 * 33 + k];
                float p1 = sP[(p_h0 + 1) * 33 + k];
                const float* vp = sKV + k * KV_STRIDE + lane;
                #pragma unroll
                for (int i = 0; i < 16; ++i) {
                    float v = vp[i * 32];
                    acc0[i] += p0 * v;
                    acc1[i] += p1 * v;
                }
            }
        }
        // next-iteration top-of-loop barrier protects sKV before regather
    }

    // epilogue: fold in the sink logit exactly as the reference does
    {
        const int hglob0 = hg * HG + p_h0;
        const int hglob1 = hglob0 + 1;

        float m0 = sM[p_h0],     l0 = sL[p_h0],     sk0 = sink[hglob0];
        float m1 = sM[p_h0 + 1], l1 = sL[p_h0 + 1], sk1 = sink[hglob1];

        float mf0 = fmaxf(m0, sk0);
        float f0  = __expf(m0 - mf0);
        float den0 = l0 * f0 + __expf(sk0 - mf0);
        float r0  = f0 / den0;

        float mf1 = fmaxf(m1, sk1);
        float f1  = __expf(m1 - mf1);
        float den1 = l1 * f1 + __expf(sk1 - mf1);
        float r1  = f1 / den1;

        float* op0 = out + ((size_t)t * HH + hglob0) * DV + lane;
        float* op1 = out + ((size_t)t * HH + hglob1) * DV + lane;
        #pragma unroll
        for (int i = 0; i < 16; ++i) {
            op0[i * 32] = acc0[i] * r0;
            op1[i * 32] = acc1[i] * r1;
        }
    }
}

extern "C" void kernel_launch(void* const* d_in, const int* in_sizes, int n_in,
                              void* d_out, int out_size)
{
    const float* q    = (const float*)d_in[0];
    const float* kv   = (const float*)d_in[1];
    const int*   topk = (const int*)d_in[2];
    const float* sink = (const float*)d_in[3];
    float*       out  = (float*)d_out;

    cudaFuncSetAttribute(mla_sparse_attn_kernel,
                         cudaFuncAttributeMaxDynamicSharedMemorySize, SMEM_BYTES);

    dim3 grid(NHG, TT);
    dim3 block(256);
    mla_sparse_attn_kernel<<<grid, block, SMEM_BYTES>>>(q, kv, topk, sink, out);
}

// round 4
// speedup vs baseline: 5.0503x; 5.0478x over previous
#include <cuda_runtime.h>
#include <cuda_fp16.h>
#include <math.h>
#include <stdint.h>

#define TT     512
#define HH     64
#define DD     576
#define DV     512
#define TOPK   1024
#define TILE   32
#define NTILES 32
#define HB     32                 // heads per block
#define KSTRIDE 584               // halves per KV/Q row in smem (1168B; 1168%128==16 -> ldsm conflict-free)
#define PSTRIDE 40                // halves per P row
#define KVBUF  (TILE * KSTRIDE)   // halves per KV buffer = 18688
#define SCALE_F (1.0f / 24.0f)    // 1/sqrt(576)

// smem byte budget
#define SMEM_BYTES (2*KVBUF*2 + HB*KSTRIDE*2 + HB*PSTRIDE*2 + 512 + 512 + 128 + 128 + 128 + 256)

__device__ __forceinline__ void ldsm_x4(uint32_t& r0, uint32_t& r1, uint32_t& r2, uint32_t& r3, uint32_t a) {
    asm volatile("ldmatrix.sync.aligned.m8n8.x4.shared.b16 {%0,%1,%2,%3}, [%4];"
                 : "=r"(r0), "=r"(r1), "=r"(r2), "=r"(r3) : "r"(a));
}
__device__ __forceinline__ void ldsm_x2(uint32_t& r0, uint32_t& r1, uint32_t a) {
    asm volatile("ldmatrix.sync.aligned.m8n8.x2.shared.b16 {%0,%1}, [%2];"
                 : "=r"(r0), "=r"(r1) : "r"(a));
}
__device__ __forceinline__ void ldsm_x2t(uint32_t& r0, uint32_t& r1, uint32_t a) {
    asm volatile("ldmatrix.sync.aligned.m8n8.x2.trans.shared.b16 {%0,%1}, [%2];"
                 : "=r"(r0), "=r"(r1) : "r"(a));
}
__device__ __forceinline__ void mma16816(float& d0, float& d1, float& d2, float& d3,
                                         uint32_t a0, uint32_t a1, uint32_t a2, uint32_t a3,
                                         uint32_t b0, uint32_t b1,
                                         float c0, float c1, float c2, float c3) {
    asm volatile("mma.sync.aligned.m16n8k16.row.col.f32.f16.f16.f32 "
                 "{%0,%1,%2,%3},{%4,%5,%6,%7},{%8,%9},{%10,%11,%12,%13};"
                 : "=f"(d0), "=f"(d1), "=f"(d2), "=f"(d3)
                 : "r"(a0), "r"(a1), "r"(a2), "r"(a3), "r"(b0), "r"(b1),
                   "f"(c0), "f"(c1), "f"(c2), "f"(c3));
}

__global__ void __launch_bounds__(256, 1)
mla_mma_kernel(const float* __restrict__ q,     // [T,H,D]
               const float* __restrict__ kv,    // [NKV,D]
               const int*   __restrict__ topk,  // [T,TOPK]
               const float* __restrict__ sink,  // [H]
               float*       __restrict__ out)   // [T,H,DV]
{
    extern __shared__ char smem_raw[];
    half*  sKVh  = (half*)smem_raw;                     // [2][KVBUF]
    half*  sQ    = sKVh + 2 * KVBUF;                    // [32][584]
    half*  sP    = sQ + HB * KSTRIDE;                   // [32][40]
    float* sPmax = (float*)(sP + HB * PSTRIDE);         // [4][32]
    float* sPsum = sPmax + 128;                         // [4][32]
    float* sM    = sPsum + 128;                         // [32]
    float* sL    = sM + 32;                             // [32]
    float* sC    = sL + 32;                             // [32]
    int*   sIdx  = (int*)(sC + 32);                     // [2][32]

    const int hblk = blockIdx.x;       // 0..1
    const int tok  = blockIdx.y;       // 0..511
    const int tid  = threadIdx.x;
    const int lt   = tid & 31;
    const int w    = tid >> 5;
    const int wrb  = w >> 2;           // rowblock (16 heads) 0/1
    const int nt   = w & 3;            // QK: token n-tile; PV: d-range

    // ---- load + convert Q (pre-scaled) ----
    {
        int h = tid >> 3, j = tid & 7;
        const float4* qs = (const float4*)(q + ((size_t)tok * HH + hblk * HB + h) * DD) + j * 18;
        half* qd = sQ + h * KSTRIDE + j * 72;
        #pragma unroll
        for (int i = 0; i < 18; ++i) {
            float4 v = qs[i];
            half2 h0 = __floats2half2_rn(v.x * SCALE_F, v.y * SCALE_F);
            half2 h1 = __floats2half2_rn(v.z * SCALE_F, v.w * SCALE_F);
            uint2 u; u.x = *(uint32_t*)&h0; u.y = *(uint32_t*)&h1;
            *(uint2*)(qd + i * 4) = u;
        }
    }
    if (tid < 32) { sM[tid] = -INFINITY; sL[tid] = 0.0f; }

    const int* tkp = topk + (size_t)tok * TOPK;

    auto gather_tile = [&](int buf, int tile) {
        int row = tid >> 3, j = tid & 7;
        int raw = tkp[tile * TILE + row];
        if (j == 0) sIdx[buf * 32 + row] = raw;
        int r2 = raw < 0 ? 0 : raw;
        const float4* src = (const float4*)(kv + (size_t)r2 * DD) + j * 18;
        half* dst = sKVh + buf * KVBUF + row * KSTRIDE + j * 72;
        float4 v[9];
        #pragma unroll
        for (int i = 0; i < 9; ++i) v[i] = src[i];
        #pragma unroll
        for (int i = 0; i < 9; ++i) {
            half2 a = __floats2half2_rn(v[i].x, v[i].y);
            half2 b = __floats2half2_rn(v[i].z, v[i].w);
            uint2 u; u.x = *(uint32_t*)&a; u.y = *(uint32_t*)&b;
            *(uint2*)(dst + i * 4) = u;
        }
        #pragma unroll
        for (int i = 0; i < 9; ++i) v[i] = src[9 + i];
        #pragma unroll
        for (int i = 0; i < 9; ++i) {
            half2 a = __floats2half2_rn(v[i].x, v[i].y);
            half2 b = __floats2half2_rn(v[i].z, v[i].w);
            uint2 u; u.x = *(uint32_t*)&a; u.y = *(uint32_t*)&b;
            *(uint2*)(dst + 36 + i * 4) = u;
        }
    };

    // prologue: gather tile 0 into buffer 0
    gather_tile(0, 0);
    __syncthreads();

    float accO[16][4];
    #pragma unroll
    for (int i = 0; i < 16; ++i) { accO[i][0] = accO[i][1] = accO[i][2] = accO[i][3] = 0.0f; }

    // precomputed smem ldmatrix base addresses
    const uint32_t skv0 = (uint32_t)__cvta_generic_to_shared(sKVh);
    const uint32_t squ  = (uint32_t)__cvta_generic_to_shared(sQ)
                        + (uint32_t)(((wrb * 16 + (lt & 15)) * KSTRIDE + (lt >> 4) * 8) * 2);
    const uint32_t sk_rowoff = (uint32_t)(((nt * 8 + (lt & 7)) * KSTRIDE + ((lt >> 3) & 1) * 8) * 2);
    const uint32_t spA  = (uint32_t)__cvta_generic_to_shared(sP)
                        + (uint32_t)(((wrb * 16 + (lt & 15)) * PSTRIDE + (lt >> 4) * 8) * 2);
    const int tok0  = (lt & 7) + ((lt >> 3) & 1) * 8;
    const int dbase = nt * 128;
    const uint32_t spv_b_off = (uint32_t)((tok0 * KSTRIDE + dbase) * 2);
    const int rowa = wrb * 16 + (lt >> 2);

    for (int kt = 0; kt < NTILES; ++kt) {
        const int cur = kt & 1;
        const uint32_t kvb = skv0 + (uint32_t)(cur * (KVBUF * 2));

        // ---- QK: S-tile [16 heads x 8 tokens], 36 k-steps ----
        float c0 = 0.f, c1 = 0.f, c2 = 0.f, c3 = 0.f;
        {
            uint32_t qa = squ;
            uint32_t ka = kvb + sk_rowoff;
            #pragma unroll 6
            for (int ks = 0; ks < 36; ++ks) {
                uint32_t a0, a1, a2, a3, b0, b1;
                ldsm_x4(a0, a1, a2, a3, qa);
                ldsm_x2(b0, b1, ka);
                mma16816(c0, c1, c2, c3, a0, a1, a2, a3, b0, b1, c0, c1, c2, c3);
                qa += 32; ka += 32;
            }
        }

        // ---- prefetch-gather next tile into the other buffer (latency hides under softmax+PV) ----
        if (kt + 1 < NTILES) gather_tile(cur ^ 1, kt + 1);

        // ---- softmax stage 1: mask + per-warp row max ----
        {
            int colb = nt * 8 + (lt & 3) * 2;
            int i0 = sIdx[cur * 32 + colb], i1 = sIdx[cur * 32 + colb + 1];
            if (i0 < 0) { c0 = -INFINITY; c2 = -INFINITY; }
            if (i1 < 0) { c1 = -INFINITY; c3 = -INFINITY; }
            float ma = fmaxf(c0, c1), mb = fmaxf(c2, c3);
            ma = fmaxf(ma, __shfl_xor_sync(0xffffffffu, ma, 1));
            ma = fmaxf(ma, __shfl_xor_sync(0xffffffffu, ma, 2));
            mb = fmaxf(mb, __shfl_xor_sync(0xffffffffu, mb, 1));
            mb = fmaxf(mb, __shfl_xor_sync(0xffffffffu, mb, 2));
            if ((lt & 3) == 0) {
                sPmax[nt * 32 + rowa]     = ma;
                sPmax[nt * 32 + rowa + 8] = mb;
            }
        }
        __syncthreads();

        // ---- softmax stage 2: global m update + carry factor ----
        if (tid < 32) {
            float mo = sM[tid];
            float mt = fmaxf(fmaxf(sPmax[tid], sPmax[32 + tid]),
                             fmaxf(sPmax[64 + tid], sPmax[96 + tid]));
            float mn = fmaxf(mo, mt);
            sC[tid] = __expf(mo - mn);      // 0 on first tile (mo = -inf)
            sM[tid] = mn;
        }
        __syncthreads();

        // ---- softmax stage 3: p = exp(s - m), write P(fp16), partial sums, rescale O ----
        {
            float mA = sM[rowa], mB = sM[rowa + 8];
            float ca = sC[rowa], cb = sC[rowa + 8];
            float p0 = (mA == -INFINITY) ? 0.f : __expf(c0 - mA);
            float p1 = (mA == -INFINITY) ? 0.f : __expf(c1 - mA);
            float p2 = (mB == -INFINITY) ? 0.f : __expf(c2 - mB);
            float p3 = (mB == -INFINITY) ? 0.f : __expf(c3 - mB);
            float sa = p0 + p1, sb = p2 + p3;
            sa += __shfl_xor_sync(0xffffffffu, sa, 1);
            sa += __shfl_xor_sync(0xffffffffu, sa, 2);
            sb += __shfl_xor_sync(0xffffffffu, sb, 1);
            sb += __shfl_xor_sync(0xffffffffu, sb, 2);
            if ((lt & 3) == 0) {
                sPsum[nt * 32 + rowa]     = sa;
                sPsum[nt * 32 + rowa + 8] = sb;
            }
            int colb = nt * 8 + (lt & 3) * 2;
            half2 hA = __floats2half2_rn(p0, p1);
            half2 hB = __floats2half2_rn(p2, p3);
            *(half2*)(sP + rowa * PSTRIDE + colb)       = hA;
            *(half2*)(sP + (rowa + 8) * PSTRIDE + colb) = hB;
            #pragma unroll
            for (int n2 = 0; n2 < 16; ++n2) {
                accO[n2][0] *= ca; accO[n2][1] *= ca;
                accO[n2][2] *= cb; accO[n2][3] *= cb;
            }
        }
        __syncthreads();

        // running denominator (warp 0, overlaps with PV below)
        if (tid < 32)
            sL[tid] = sL[tid] * sC[tid]
                    + sPsum[tid] + sPsum[32 + tid] + sPsum[64 + tid] + sPsum[96 + tid];

        // ---- PV: O[16 heads x 128 d] += P[16x32] @ V[32x128] ----
        {
            uint32_t a0, a1, a2, a3, e0, e1, e2, e3;
            ldsm_x4(a0, a1, a2, a3, spA);        // k-step 0 (tokens 0-15)
            ldsm_x4(e0, e1, e2, e3, spA + 32);   // k-step 1 (tokens 16-31)
            uint32_t bbase = kvb + spv_b_off;
            #pragma unroll
            for (int n2 = 0; n2 < 16; ++n2) {
                uint32_t b0, b1;
                uint32_t ba = bbase + (uint32_t)(n2 * 16);
                ldsm_x2t(b0, b1, ba);
                mma16816(accO[n2][0], accO[n2][1], accO[n2][2], accO[n2][3],
                         a0, a1, a2, a3, b0, b1,
                         accO[n2][0], accO[n2][1], accO[n2][2], accO[n2][3]);
                ldsm_x2t(b0, b1, ba + (uint32_t)(16 * KSTRIDE * 2));
                mma16816(accO[n2][0], accO[n2][1], accO[n2][2], accO[n2][3],
                         e0, e1, e2, e3, b0, b1,
                         accO[n2][0], accO[n2][1], accO[n2][2], accO[n2][3]);
            }
        }
        __syncthreads();   // protects: gather buf for next QK, sP reuse, sKVh reuse, final sL
    }

    // ---- epilogue: sink-aware normalization, write out ----
    {
        const int rowb = rowa + 8;
        const int hgA = hblk * HB + rowa;
        const int hgB = hblk * HB + rowb;

        float mA = sM[rowa], lA = sL[rowa], skA = sink[hgA];
        float mB = sM[rowb], lB = sL[rowb], skB = sink[hgB];

        float mfA = fmaxf(mA, skA);
        float fA  = __expf(mA - mfA);
        float rA  = fA / (lA * fA + __expf(skA - mfA));

        float mfB = fmaxf(mB, skB);
        float fB  = __expf(mB - mfB);
        float rB  = fB / (lB * fB + __expf(skB - mfB));

        float* ob = out + ((size_t)tok * HH + hblk * HB) * DV;
        #pragma unroll
        for (int n2 = 0; n2 < 16; ++n2) {
            int d = dbase + n2 * 8 + (lt & 3) * 2;
            float2 va = make_float2(accO[n2][0] * rA, accO[n2][1] * rA);
            float2 vb = make_float2(accO[n2][2] * rB, accO[n2][3] * rB);
            *(float2*)(ob + (size_t)rowa * DV + d) = va;
            *(float2*)(ob + (size_t)rowb * DV + d) = vb;
        }
    }
}

extern "C" void kernel_launch(void* const* d_in, const int* in_sizes, int n_in,
                              void* d_out, int out_size)
{
    const float* q    = (const float*)d_in[0];
    const float* kv   = (const float*)d_in[1];
    const int*   topk = (const int*)d_in[2];
    const float* sink = (const float*)d_in[3];
    float*       out  = (float*)d_out;

    cudaFuncSetAttribute(mla_mma_kernel,
                         cudaFuncAttributeMaxDynamicSharedMemorySize, SMEM_BYTES);

    dim3 grid(HH / HB, TT);   // (2, 512)
    dim3 block(256);
    mla_mma_kernel<<<grid, block, SMEM_BYTES>>>(q, kv, topk, sink, out);
}

// round 5
// speedup vs baseline: 5.8385x; 1.1561x over previous
#include <cuda_runtime.h>
#include <cuda_fp16.h>
#include <math.h>
#include <stdint.h>

#define TT     512
#define HH     64
#define DD     576
#define DV     512
#define TOPK   1024
#define TILE   32
#define NTILES 32
#define HB     32
#define KSTRIDE 584               // halves per KV/Q smem row
#define PSTRIDE 40                // halves per P row
#define KVBUF  (TILE * KSTRIDE)   // 18688 halves
#define SCALE_F (1.0f / 24.0f)

// smem: sKV 2*KVBUF*2 | sP 32*40*2 | sPart 4*32*8*4 | sLp 64*4 | sIdx 2*32*4
#define SMEM_BYTES (2*KVBUF*2 + HB*PSTRIDE*2 + 4*32*8*4 + 64*4 + 2*32*4 + 256)

__device__ __forceinline__ void ldsm_x4(uint32_t& r0, uint32_t& r1, uint32_t& r2, uint32_t& r3, uint32_t a) {
    asm volatile("ldmatrix.sync.aligned.m8n8.x4.shared.b16 {%0,%1,%2,%3}, [%4];"
                 : "=r"(r0), "=r"(r1), "=r"(r2), "=r"(r3) : "r"(a));
}
__device__ __forceinline__ void ldsm_x2t(uint32_t& r0, uint32_t& r1, uint32_t a) {
    asm volatile("ldmatrix.sync.aligned.m8n8.x2.trans.shared.b16 {%0,%1}, [%2];"
                 : "=r"(r0), "=r"(r1) : "r"(a));
}
__device__ __forceinline__ void mma16816(float& d0, float& d1, float& d2, float& d3,
                                         uint32_t a0, uint32_t a1, uint32_t a2, uint32_t a3,
                                         uint32_t b0, uint32_t b1,
                                         float c0, float c1, float c2, float c3) {
    asm volatile("mma.sync.aligned.m16n8k16.row.col.f32.f16.f16.f32 "
                 "{%0,%1,%2,%3},{%4,%5,%6,%7},{%8,%9},{%10,%11,%12,%13};"
                 : "=f"(d0), "=f"(d1), "=f"(d2), "=f"(d3)
                 : "r"(a0), "r"(a1), "r"(a2), "r"(a3), "r"(b0), "r"(b1),
                   "f"(c0), "f"(c1), "f"(c2), "f"(c3));
}

__global__ void __launch_bounds__(256, 1)
mla_v2_kernel(const float* __restrict__ q,     // [T,H,D]
              const float* __restrict__ kv,    // [NKV,D]
              const int*   __restrict__ topk,  // [T,TOPK]
              const float* __restrict__ sink,  // [H]
              float*       __restrict__ out)   // [T,H,DV]
{
    extern __shared__ char smem_raw[];
    half*  sKVh  = (half*)smem_raw;                 // [2][KVBUF]
    half*  sP    = sKVh + 2 * KVBUF;                // [32][40]
    float* sPart = (float*)(sP + HB * PSTRIDE);     // [4][32][8]
    float* sLp   = sPart + 4 * 32 * 8;              // [2][32]
    int*   sIdx  = (int*)(sLp + 64);                // [2][32]

    const int hblk = blockIdx.x;       // 0..1
    const int tok  = blockIdx.y;       // 0..511
    const int tid  = threadIdx.x;
    const int lt   = tid & 31;
    const int w    = tid >> 5;
    const int wrb  = w >> 2;           // head rowblock: 16 heads
    const int nt   = (w >> 1) & 1;     // token half: 16 tokens
    const int ks   = w & 1;            // k-split half: 288 dims
    const int pair = w >> 1;           // sPart slot

    const uint32_t skv0 = (uint32_t)__cvta_generic_to_shared(sKVh);
    const uint32_t spb  = (uint32_t)__cvta_generic_to_shared(sP);

    // ---- stage Q (pre-scaled) into sKV buf0, load A-fragments to registers ----
    {
        int h = tid >> 3, j = tid & 7;
        const float4* qs = (const float4*)(q + ((size_t)tok * HH + hblk * HB + h) * DD) + j * 18;
        half* qd = sKVh + h * KSTRIDE + j * 72;
        #pragma unroll
        for (int i = 0; i < 18; ++i) {
            float4 v = qs[i];
            half2 h0 = __floats2half2_rn(v.x * SCALE_F, v.y * SCALE_F);
            half2 h1 = __floats2half2_rn(v.z * SCALE_F, v.w * SCALE_F);
            uint2 u; u.x = *(uint32_t*)&h0; u.y = *(uint32_t*)&h1;
            *(uint2*)(qd + i * 4) = u;
        }
    }
    __syncthreads();

    uint32_t qf[72];
    {
        uint32_t qa = skv0 + (uint32_t)(((wrb * 16 + (lt & 15)) * KSTRIDE + ks * 288 + (lt >> 4) * 8) * 2);
        #pragma unroll
        for (int s = 0; s < 18; ++s) {
            ldsm_x4(qf[4*s], qf[4*s+1], qf[4*s+2], qf[4*s+3], qa);
            qa += 32;
        }
    }
    __syncthreads();   // Q frags read before gather overwrites buf0

    const int* tkp = topk + (size_t)tok * TOPK;

    // ---- gather tile 0 into buf0 (all 256 threads) ----
    {
        int row = tid >> 3, j = tid & 7;
        int raw = tkp[row];
        if (j == 0) sIdx[row] = raw;
        int r2 = raw < 0 ? 0 : raw;
        const float4* src = (const float4*)(kv + (size_t)r2 * DD) + j * 18;
        half* dst = sKVh + row * KSTRIDE + j * 72;
        #pragma unroll
        for (int b = 0; b < 2; ++b) {
            float4 v[9];
            #pragma unroll
            for (int i = 0; i < 9; ++i) v[i] = src[b * 9 + i];
            #pragma unroll
            for (int i = 0; i < 9; ++i) {
                half2 a = __floats2half2_rn(v[i].x, v[i].y);
                half2 c = __floats2half2_rn(v[i].z, v[i].w);
                uint2 u; u.x = *(uint32_t*)&a; u.y = *(uint32_t*)&c;
                *(uint2*)(dst + b * 36 + i * 4) = u;
            }
        }
    }
    __syncthreads();

    float accO[2][8][4];
    #pragma unroll
    for (int m = 0; m < 2; ++m)
        #pragma unroll
        for (int n = 0; n < 8; ++n)
            accO[m][n][0] = accO[m][n][1] = accO[m][n][2] = accO[m][n][3] = 0.0f;

    float rs0 = 0.0f, rs1 = 0.0f;      // running row-sums (ks==0 warps)

    // precomputed offsets
    const uint32_t qkB_off = (uint32_t)(((nt * 16 + (lt & 15)) * KSTRIDE + ks * 288 + (lt >> 4) * 8) * 2);
    const int tok0 = (lt & 7) + ((lt >> 3) & 1) * 8;
    const uint32_t pvB_off = (uint32_t)((tok0 * KSTRIDE + w * 64) * 2);
    const int grow_i = ((w >> 1) & 3) * 8 + (lt >> 2);   // gather row for ks1 warps
    const int gseg   = lt & 3;

    for (int kt = 0; kt < NTILES; ++kt) {
        const int cur = kt & 1;
        const uint32_t kvb = skv0 + (uint32_t)(cur * (KVBUF * 2));
        const bool hasNext = (kt + 1 < NTILES);

        // ---- QK: warp tile [16h x 16t], 18 k-steps, A in registers ----
        float c00 = 0.f, c01 = 0.f, c02 = 0.f, c03 = 0.f;
        float c10 = 0.f, c11 = 0.f, c12 = 0.f, c13 = 0.f;
        {
            uint32_t ka = kvb + qkB_off;
            #pragma unroll
            for (int s = 0; s < 18; ++s) {
                uint32_t b0, b1, b2, b3;
                ldsm_x4(b0, b1, b2, b3, ka); ka += 32;
                mma16816(c00, c01, c02, c03, qf[4*s], qf[4*s+1], qf[4*s+2], qf[4*s+3],
                         b0, b2, c00, c01, c02, c03);
                mma16816(c10, c11, c12, c13, qf[4*s], qf[4*s+1], qf[4*s+2], qf[4*s+3],
                         b1, b3, c10, c11, c12, c13);
            }
        }

        // ks1 warps: start gather of next tile (issue first LDG batch pre-barrier)
        const float4* gsrc = 0; half* gdst = 0;
        float4 gv[9];
        if (ks == 1 && hasNext) {
            int raw = tkp[(kt + 1) * TILE + grow_i];
            if (gseg == 0) sIdx[(cur ^ 1) * 32 + grow_i] = raw;
            int r2 = raw < 0 ? 0 : raw;
            gsrc = (const float4*)(kv + (size_t)r2 * DD) + gseg * 36;
            gdst = sKVh + (cur ^ 1) * KVBUF + grow_i * KSTRIDE + gseg * 144;
            #pragma unroll
            for (int i = 0; i < 9; ++i) gv[i] = gsrc[i];
        }

        // ks1 warps export partial S
        if (ks == 1) {
            float* pb = sPart + pair * 256 + lt * 8;
            *(float4*)pb       = make_float4(c00, c01, c02, c03);
            *(float4*)(pb + 4) = make_float4(c10, c11, c12, c13);
        }
        __syncthreads();   // A: partials visible; prev-PV done before gather STS

        if (ks == 1) {
            if (hasNext) {
                #pragma unroll
                for (int b = 0; b < 4; ++b) {
                    if (b > 0) {
                        #pragma unroll
                        for (int i = 0; i < 9; ++i) gv[i] = gsrc[b * 9 + i];
                    }
                    #pragma unroll
                    for (int i = 0; i < 9; ++i) {
                        half2 a = __floats2half2_rn(gv[i].x, gv[i].y);
                        half2 c = __floats2half2_rn(gv[i].z, gv[i].w);
                        uint2 u; u.x = *(uint32_t*)&a; u.y = *(uint32_t*)&c;
                        *(uint2*)(gdst + b * 36 + i * 4) = u;
                    }
                }
            }
        } else {
            // ---- softmax (fixed base): add partner partial, mask, exp, write P ----
            const float* pb = sPart + pair * 256 + lt * 8;
            float4 pA = *(const float4*)pb;
            float4 pB = *(const float4*)(pb + 4);
            c00 += pA.x; c01 += pA.y; c02 += pA.z; c03 += pA.w;
            c10 += pB.x; c11 += pB.y; c12 += pB.z; c13 += pB.w;

            const int tb   = nt * 16;
            const int rowa = wrb * 16 + (lt >> 2);
            #pragma unroll
            for (int j = 0; j < 2; ++j) {
                int t0 = tb + j * 8 + (lt & 3) * 2;
                int i0 = sIdx[cur * 32 + t0];
                int i1 = sIdx[cur * 32 + t0 + 1];
                float s0 = j ? c10 : c00, s1 = j ? c11 : c01;
                float s2 = j ? c12 : c02, s3 = j ? c13 : c03;
                float p0 = (i0 < 0) ? 0.f : __expf(s0);
                float p1 = (i1 < 0) ? 0.f : __expf(s1);
                float p2 = (i0 < 0) ? 0.f : __expf(s2);
                float p3 = (i1 < 0) ? 0.f : __expf(s3);
                rs0 += p0 + p1;
                rs1 += p2 + p3;
                half2 hA = __floats2half2_rn(p0, p1);
                half2 hB = __floats2half2_rn(p2, p3);
                *(half2*)(sP + rowa * PSTRIDE + t0)       = hA;
                *(half2*)(sP + (rowa + 8) * PSTRIDE + t0) = hB;
            }
        }
        __syncthreads();   // B: P + next KV tile visible

        // ---- PV: warp tile [32h x 64d] = P[32x32] @ V[32x64] ----
        {
            uint32_t ap[2][2][4];
            #pragma unroll
            for (int mi = 0; mi < 2; ++mi)
                #pragma unroll
                for (int k2 = 0; k2 < 2; ++k2) {
                    uint32_t aa = spb + (uint32_t)(((mi * 16 + (lt & 15)) * PSTRIDE + k2 * 16 + (lt >> 4) * 8) * 2);
                    ldsm_x4(ap[mi][k2][0], ap[mi][k2][1], ap[mi][k2][2], ap[mi][k2][3], aa);
                }
            uint32_t bbase = kvb + pvB_off;
            #pragma unroll
            for (int n2 = 0; n2 < 8; ++n2) {
                uint32_t b0, b1;
                uint32_t ba = bbase + (uint32_t)(n2 * 16);
                ldsm_x2t(b0, b1, ba);
                #pragma unroll
                for (int mi = 0; mi < 2; ++mi)
                    mma16816(accO[mi][n2][0], accO[mi][n2][1], accO[mi][n2][2], accO[mi][n2][3],
                             ap[mi][0][0], ap[mi][0][1], ap[mi][0][2], ap[mi][0][3], b0, b1,
                             accO[mi][n2][0], accO[mi][n2][1], accO[mi][n2][2], accO[mi][n2][3]);
                ldsm_x2t(b0, b1, ba + (uint32_t)(16 * KSTRIDE * 2));
                #pragma unroll
                for (int mi = 0; mi < 2; ++mi)
                    mma16816(accO[mi][n2][0], accO[mi][n2][1], accO[mi][n2][2], accO[mi][n2][3],
                             ap[mi][1][0], ap[mi][1][1], ap[mi][1][2], ap[mi][1][3], b0, b1,
                             accO[mi][n2][0], accO[mi][n2][1], accO[mi][n2][2], accO[mi][n2][3]);
            }
        }
        __syncthreads();   // protects sP / sKV / sPart reuse next iteration
    }

    // ---- epilogue: export row sums, sink-aware normalize, write out ----
    if (ks == 0) {
        rs0 += __shfl_xor_sync(0xffffffffu, rs0, 1);
        rs0 += __shfl_xor_sync(0xffffffffu, rs0, 2);
        rs1 += __shfl_xor_sync(0xffffffffu, rs1, 1);
        rs1 += __shfl_xor_sync(0xffffffffu, rs1, 2);
        if ((lt & 3) == 0) {
            int r = wrb * 16 + (lt >> 2);
            sLp[nt * 32 + r]     = rs0;
            sLp[nt * 32 + r + 8] = rs1;
        }
    }
    __syncthreads();

    {
        float* ob = out + ((size_t)tok * HH + hblk * HB) * DV;
        #pragma unroll
        for (int mi = 0; mi < 2; ++mi) {
            int r0 = mi * 16 + (lt >> 2);
            int r1 = r0 + 8;
            float d0 = sLp[r0] + sLp[32 + r0] + __expf(sink[hblk * HB + r0]);
            float d1 = sLp[r1] + sLp[32 + r1] + __expf(sink[hblk * HB + r1]);
            float rc0 = 1.0f / d0;
            float rc1 = 1.0f / d1;
            #pragma unroll
            for (int n2 = 0; n2 < 8; ++n2) {
                int d = w * 64 + n2 * 8 + (lt & 3) * 2;
                *(float2*)(ob + (size_t)r0 * DV + d) =
                    make_float2(accO[mi][n2][0] * rc0, accO[mi][n2][1] * rc0);
                *(float2*)(ob + (size_t)r1 * DV + d) =
                    make_float2(accO[mi][n2][2] * rc1, accO[mi][n2][3] * rc1);
            }
        }
    }
}

extern "C" void kernel_launch(void* const* d_in, const int* in_sizes, int n_in,
                              void* d_out, int out_size)
{
    const float* q    = (const float*)d_in[0];
    const float* kv   = (const float*)d_in[1];
    const int*   topk = (const int*)d_in[2];
    const float* sink = (const float*)d_in[3];
    float*       out  = (float*)d_out;

    cudaFuncSetAttribute(mla_v2_kernel,
                         cudaFuncAttributeMaxDynamicSharedMemorySize, SMEM_BYTES);

    dim3 grid(HH / HB, TT);   // (2, 512)
    dim3 block(256);
    mla_v2_kernel<<<grid, block, SMEM_BYTES>>>(q, kv, topk, sink, out);
}

// round 6
// speedup vs baseline: 9.7414x; 1.6685x over previous
#include <cuda_runtime.h>
#include <cuda_fp16.h>
#include <math.h>
#include <stdint.h>

#define TT     512
#define HH     64
#define DD     576
#define DV     512
#define NKV    8192
#define TOPK   1024
#define TILE   32
#define NTILES 32
#define HB     32
#define KSTRIDE 584               // halves per KV/Q smem row (1168 B)
#define PSTRIDE 40                // halves per P row
#define KVBUF  (TILE * KSTRIDE)   // 18688 halves
#define SCALE_F (1.0f / 24.0f)

// smem: sKV 2*KVBUF*2 | sP 32*40*2 | sPart 4*32*8*4 | sLp 64*4 | sIdx 2*32*4
#define SMEM_BYTES (2*KVBUF*2 + HB*PSTRIDE*2 + 4*32*8*4 + 64*4 + 2*32*4 + 256)

// fp16 copy of the latent cache, produced by a prepass kernel each launch
__device__ __align__(16) half g_kvh[(size_t)NKV * DD];

__global__ void __launch_bounds__(256)
kv_to_half_kernel(const float* __restrict__ kv)
{
    size_t i = (size_t)blockIdx.x * 256 + threadIdx.x;   // one float4 each
    float4 v = ((const float4*)kv)[i];
    half2 a = __floats2half2_rn(v.x, v.y);
    half2 b = __floats2half2_rn(v.z, v.w);
    uint2 u; u.x = *(uint32_t*)&a; u.y = *(uint32_t*)&b;
    ((uint2*)g_kvh)[i] = u;
}

__device__ __forceinline__ void ldsm_x4(uint32_t& r0, uint32_t& r1, uint32_t& r2, uint32_t& r3, uint32_t a) {
    asm volatile("ldmatrix.sync.aligned.m8n8.x4.shared.b16 {%0,%1,%2,%3}, [%4];"
                 : "=r"(r0), "=r"(r1), "=r"(r2), "=r"(r3) : "r"(a));
}
__device__ __forceinline__ void ldsm_x2t(uint32_t& r0, uint32_t& r1, uint32_t a) {
    asm volatile("ldmatrix.sync.aligned.m8n8.x2.trans.shared.b16 {%0,%1}, [%2];"
                 : "=r"(r0), "=r"(r1) : "r"(a));
}
__device__ __forceinline__ void mma16816(float& d0, float& d1, float& d2, float& d3,
                                         uint32_t a0, uint32_t a1, uint32_t a2, uint32_t a3,
                                         uint32_t b0, uint32_t b1,
                                         float c0, float c1, float c2, float c3) {
    asm volatile("mma.sync.aligned.m16n8k16.row.col.f32.f16.f16.f32 "
                 "{%0,%1,%2,%3},{%4,%5,%6,%7},{%8,%9},{%10,%11,%12,%13};"
                 : "=f"(d0), "=f"(d1), "=f"(d2), "=f"(d3)
                 : "r"(a0), "r"(a1), "r"(a2), "r"(a3), "r"(b0), "r"(b1),
                   "f"(c0), "f"(c1), "f"(c2), "f"(c3));
}

__global__ void __launch_bounds__(256, 1)
mla_v3_kernel(const float* __restrict__ q,     // [T,H,D]
              const int*   __restrict__ topk,  // [T,TOPK]
              const float* __restrict__ sink,  // [H]
              float*       __restrict__ out)   // [T,H,DV]
{
    extern __shared__ char smem_raw[];
    half*  sKVh  = (half*)smem_raw;                 // [2][KVBUF]
    half*  sP    = sKVh + 2 * KVBUF;                // [32][40]
    float* sPart = (float*)(sP + HB * PSTRIDE);     // [4][32][8]
    float* sLp   = sPart + 4 * 32 * 8;              // [2][32]
    int*   sIdx  = (int*)(sLp + 64);                // [2][32]

    const int hblk = blockIdx.x;       // 0..1
    const int tok  = blockIdx.y;       // 0..511
    const int tid  = threadIdx.x;
    const int lt   = tid & 31;
    const int w    = tid >> 5;
    const int wrb  = w >> 2;           // head rowblock: 16 heads
    const int nt   = (w >> 1) & 1;     // token half: 16 tokens
    const int ks   = w & 1;            // k-split half: 288 dims
    const int pair = w >> 1;           // sPart slot

    const uint32_t skv0 = (uint32_t)__cvta_generic_to_shared(sKVh);
    const uint32_t spb  = (uint32_t)__cvta_generic_to_shared(sP);

    // ---- stage Q (pre-scaled) into sKV buf0 — coalesced: lane j owns 16B columns ----
    {
        int h = tid >> 3, j = tid & 7;
        const float4* qs = (const float4*)(q + ((size_t)tok * HH + hblk * HB + h) * DD) + j;
        half* qd = sKVh + h * KSTRIDE;
        #pragma unroll
        for (int i = 0; i < 18; ++i) {
            float4 v = qs[i * 8];                     // bytes j*16 + i*128 (1 line / 8 lanes)
            half2 h0 = __floats2half2_rn(v.x * SCALE_F, v.y * SCALE_F);
            half2 h1 = __floats2half2_rn(v.z * SCALE_F, v.w * SCALE_F);
            uint2 u; u.x = *(uint32_t*)&h0; u.y = *(uint32_t*)&h1;
            *(uint2*)(qd + j * 4 + i * 32) = u;       // element-matched half offset
        }
    }
    __syncthreads();

    uint32_t qf[72];
    {
        uint32_t qa = skv0 + (uint32_t)(((wrb * 16 + (lt & 15)) * KSTRIDE + ks * 288 + (lt >> 4) * 8) * 2);
        #pragma unroll
        for (int s = 0; s < 18; ++s) {
            ldsm_x4(qf[4*s], qf[4*s+1], qf[4*s+2], qf[4*s+3], qa);
            qa += 32;
        }
    }
    __syncthreads();   // Q frags read before gather overwrites buf0

    const int* tkp = topk + (size_t)tok * TOPK;

    // ---- gather tile 0 into buf0: pure fp16 copy, lane j = 16B column ----
    {
        int row = tid >> 3, j = tid & 7;
        int raw = tkp[row];
        if (j == 0) sIdx[row] = raw;
        int r2 = raw < 0 ? 0 : raw;
        const uint4* src = (const uint4*)(g_kvh + (size_t)r2 * DD) + j;
        uint4* dst = (uint4*)(sKVh + row * KSTRIDE) + j;
        #pragma unroll
        for (int i = 0; i < 9; ++i) dst[i * 8] = src[i * 8];   // bytes j*16 + i*128
    }
    __syncthreads();

    float accO[2][8][4];
    #pragma unroll
    for (int m = 0; m < 2; ++m)
        #pragma unroll
        for (int n = 0; n < 8; ++n)
            accO[m][n][0] = accO[m][n][1] = accO[m][n][2] = accO[m][n][3] = 0.0f;

    float rs0 = 0.0f, rs1 = 0.0f;      // running row-sums (ks==0 warps)

    // precomputed offsets
    const uint32_t qkB_off = (uint32_t)(((nt * 16 + (lt & 15)) * KSTRIDE + ks * 288 + (lt >> 4) * 8) * 2);
    const int tok0 = (lt & 7) + ((lt >> 3) & 1) * 8;
    const uint32_t pvB_off = (uint32_t)((tok0 * KSTRIDE + w * 64) * 2);
    const int grow = ((w >> 1) & 3) * 8 + (lt >> 2);   // gather row (ks1 warps: 4 lanes/row)
    const int gseg = lt & 3;                            // 16B column within row

    for (int kt = 0; kt < NTILES; ++kt) {
        const int cur = kt & 1;
        const uint32_t kvb = skv0 + (uint32_t)(cur * (KVBUF * 2));
        const bool hasNext = (kt + 1 < NTILES);

        // ---- QK: warp tile [16h x 16t], 18 k-steps, A in registers ----
        float c00 = 0.f, c01 = 0.f, c02 = 0.f, c03 = 0.f;
        float c10 = 0.f, c11 = 0.f, c12 = 0.f, c13 = 0.f;
        {
            uint32_t ka = kvb + qkB_off;
            #pragma unroll
            for (int s = 0; s < 18; ++s) {
                uint32_t b0, b1, b2, b3;
                ldsm_x4(b0, b1, b2, b3, ka); ka += 32;
                mma16816(c00, c01, c02, c03, qf[4*s], qf[4*s+1], qf[4*s+2], qf[4*s+3],
                         b0, b2, c00, c01, c02, c03);
                mma16816(c10, c11, c12, c13, qf[4*s], qf[4*s+1], qf[4*s+2], qf[4*s+3],
                         b1, b3, c10, c11, c12, c13);
            }
        }

        // ks1 warps: start gather of next tile (coalesced 16B-copy; 9 LDGs pre-barrier)
        const uint4* gsrc = 0; uint4* gdst = 0;
        uint4 gv[9];
        if (ks == 1 && hasNext) {
            int raw = tkp[(kt + 1) * TILE + grow];
            if (gseg == 0) sIdx[(cur ^ 1) * 32 + grow] = raw;
            int r2 = raw < 0 ? 0 : raw;
            gsrc = (const uint4*)(g_kvh + (size_t)r2 * DD) + gseg;
            gdst = (uint4*)(sKVh + (cur ^ 1) * KVBUF + grow * KSTRIDE) + gseg;
            #pragma unroll
            for (int i = 0; i < 9; ++i) gv[i] = gsrc[i * 4];   // bytes gseg*16 + i*64
        }

        // ks1 warps export partial S
        if (ks == 1) {
            float* pb = sPart + pair * 256 + lt * 8;
            *(float4*)pb       = make_float4(c00, c01, c02, c03);
            *(float4*)(pb + 4) = make_float4(c10, c11, c12, c13);
        }
        __syncthreads();   // A: partials visible

        if (ks == 1) {
            if (hasNext) {
                #pragma unroll
                for (int i = 0; i < 9; ++i) gdst[i * 4] = gv[i];
                #pragma unroll
                for (int i = 9; i < 18; ++i) gdst[i * 4] = gsrc[i * 4];
            }
        } else {
            // ---- softmax (fixed base 0): add partner partial, mask, exp, write P ----
            const float* pb = sPart + pair * 256 + lt * 8;
            float4 pA = *(const float4*)pb;
            float4 pB = *(const float4*)(pb + 4);
            c00 += pA.x; c01 += pA.y; c02 += pA.z; c03 += pA.w;
            c10 += pB.x; c11 += pB.y; c12 += pB.z; c13 += pB.w;

            const int tb   = nt * 16;
            const int rowa = wrb * 16 + (lt >> 2);
            #pragma unroll
            for (int j = 0; j < 2; ++j) {
                int t0 = tb + j * 8 + (lt & 3) * 2;
                int i0 = sIdx[cur * 32 + t0];
                int i1 = sIdx[cur * 32 + t0 + 1];
                float s0 = j ? c10 : c00, s1 = j ? c11 : c01;
                float s2 = j ? c12 : c02, s3 = j ? c13 : c03;
                float p0 = (i0 < 0) ? 0.f : __expf(s0);
                float p1 = (i1 < 0) ? 0.f : __expf(s1);
                float p2 = (i0 < 0) ? 0.f : __expf(s2);
                float p3 = (i1 < 0) ? 0.f : __expf(s3);
                rs0 += p0 + p1;
                rs1 += p2 + p3;
                half2 hA = __floats2half2_rn(p0, p1);
                half2 hB = __floats2half2_rn(p2, p3);
                *(half2*)(sP + rowa * PSTRIDE + t0)       = hA;
                *(half2*)(sP + (rowa + 8) * PSTRIDE + t0) = hB;
            }
        }
        __syncthreads();   // B: P + next KV tile visible

        // ---- PV: warp tile [32h x 64d] = P[32x32] @ V[32x64] ----
        {
            uint32_t ap[2][2][4];
            #pragma unroll
            for (int mi = 0; mi < 2; ++mi)
                #pragma unroll
                for (int k2 = 0; k2 < 2; ++k2) {
                    uint32_t aa = spb + (uint32_t)(((mi * 16 + (lt & 15)) * PSTRIDE + k2 * 16 + (lt >> 4) * 8) * 2);
                    ldsm_x4(ap[mi][k2][0], ap[mi][k2][1], ap[mi][k2][2], ap[mi][k2][3], aa);
                }
            uint32_t bbase = kvb + pvB_off;
            #pragma unroll
            for (int n2 = 0; n2 < 8; ++n2) {
                uint32_t b0, b1;
                uint32_t ba = bbase + (uint32_t)(n2 * 16);
                ldsm_x2t(b0, b1, ba);
                #pragma unroll
                for (int mi = 0; mi < 2; ++mi)
                    mma16816(accO[mi][n2][0], accO[mi][n2][1], accO[mi][n2][2], accO[mi][n2][3],
                             ap[mi][0][0], ap[mi][0][1], ap[mi][0][2], ap[mi][0][3], b0, b1,
                             accO[mi][n2][0], accO[mi][n2][1], accO[mi][n2][2], accO[mi][n2][3]);
                ldsm_x2t(b0, b1, ba + (uint32_t)(16 * KSTRIDE * 2));
                #pragma unroll
                for (int mi = 0; mi < 2; ++mi)
                    mma16816(accO[mi][n2][0], accO[mi][n2][1], accO[mi][n2][2], accO[mi][n2][3],
                             ap[mi][1][0], ap[mi][1][1], ap[mi][1][2], ap[mi][1][3], b0, b1,
                             accO[mi][n2][0], accO[mi][n2][1], accO[mi][n2][2], accO[mi][n2][3]);
            }
        }
        __syncthreads();   // protects sP / sKV / sPart reuse next iteration
    }

    // ---- epilogue: export row sums, sink-aware normalize, write out ----
    if (ks == 0) {
        rs0 += __shfl_xor_sync(0xffffffffu, rs0, 1);
        rs0 += __shfl_xor_sync(0xffffffffu, rs0, 2);
        rs1 += __shfl_xor_sync(0xffffffffu, rs1, 1);
        rs1 += __shfl_xor_sync(0xffffffffu, rs1, 2);
        if ((lt & 3) == 0) {
            int r = wrb * 16 + (lt >> 2);
            sLp[nt * 32 + r]     = rs0;
            sLp[nt * 32 + r + 8] = rs1;
        }
    }
    __syncthreads();

    {
        float* ob = out + ((size_t)tok * HH + hblk * HB) * DV;
        #pragma unroll
        for (int mi = 0; mi < 2; ++mi) {
            int r0 = mi * 16 + (lt >> 2);
            int r1 = r0 + 8;
            float d0 = sLp[r0] + sLp[32 + r0] + __expf(sink[hblk * HB + r0]);
            float d1 = sLp[r1] + sLp[32 + r1] + __expf(sink[hblk * HB + r1]);
            float rc0 = 1.0f / d0;
            float rc1 = 1.0f / d1;
            #pragma unroll
            for (int n2 = 0; n2 < 8; ++n2) {
                int d = w * 64 + n2 * 8 + (lt & 3) * 2;
                *(float2*)(ob + (size_t)r0 * DV + d) =
                    make_float2(accO[mi][n2][0] * rc0, accO[mi][n2][1] * rc0);
                *(float2*)(ob + (size_t)r1 * DV + d) =
                    make_float2(accO[mi][n2][2] * rc1, accO[mi][n2][3] * rc1);
            }
        }
    }
}

extern "C" void kernel_launch(void* const* d_in, const int* in_sizes, int n_in,
                              void* d_out, int out_size)
{
    const float* q    = (const float*)d_in[0];
    const float* kv   = (const float*)d_in[1];
    const int*   topk = (const int*)d_in[2];
    const float* sink = (const float*)d_in[3];
    float*       out  = (float*)d_out;

    // prepass: fp32 KV cache -> fp16 device-global copy
    kv_to_half_kernel<<<(NKV * DD / 4) / 256, 256>>>(kv);

    cudaFuncSetAttribute(mla_v3_kernel,
                         cudaFuncAttributeMaxDynamicSharedMemorySize, SMEM_BYTES);

    dim3 grid(HH / HB, TT);   // (2, 512)
    dim3 block(256);
    mla_v3_kernel<<<grid, block, SMEM_BYTES>>>(q, topk, sink, out);
}

// round 8
// speedup vs baseline: 11.1126x; 1.1408x over previous
#include <cuda_runtime.h>
#include <cuda_fp16.h>
#include <math.h>
#include <stdint.h>

#define TT     512
#define HH     64
#define DD     576
#define DV     512
#define NKV    8192
#define TOPK   1024
#define TILE   32
#define NTILES 32
#define HB     32
#define KSTRIDE 584               // halves per KV/Q smem row (1168 B)
#define PSTRIDE 40                // halves per P row
#define KVBUF  (TILE * KSTRIDE)   // 18688 halves
#define SCALE_F (1.0f / 24.0f)

// smem: sKV 2*KVBUF*2 | sP 32*40*2 | sPart 8*32*4*4 | sLp 128*4 | sIdx 2*32*4
#define SMEM_BYTES (2*KVBUF*2 + HB*PSTRIDE*2 + 8*32*4*4 + 128*4 + 2*32*4 + 256)

// fp16 copy of the latent cache, produced by a prepass kernel each launch
__device__ __align__(16) half g_kvh[(size_t)NKV * DD];

__global__ void __launch_bounds__(256)
kv_to_half_kernel(const float* __restrict__ kv)
{
    size_t i = (size_t)blockIdx.x * 256 + threadIdx.x;   // one float4 each
    float4 v = ((const float4*)kv)[i];
    half2 a = __floats2half2_rn(v.x, v.y);
    half2 b = __floats2half2_rn(v.z, v.w);
    uint2 u; u.x = *(uint32_t*)&a; u.y = *(uint32_t*)&b;
    ((uint2*)g_kvh)[i] = u;
}

__device__ __forceinline__ void ldsm_x4(uint32_t& r0, uint32_t& r1, uint32_t& r2, uint32_t& r3, uint32_t a) {
    asm volatile("ldmatrix.sync.aligned.m8n8.x4.shared.b16 {%0,%1,%2,%3}, [%4];"
                 : "=r"(r0), "=r"(r1), "=r"(r2), "=r"(r3) : "r"(a));
}
__device__ __forceinline__ void ldsm_x4t(uint32_t& r0, uint32_t& r1, uint32_t& r2, uint32_t& r3, uint32_t a) {
    asm volatile("ldmatrix.sync.aligned.m8n8.x4.trans.shared.b16 {%0,%1,%2,%3}, [%4];"
                 : "=r"(r0), "=r"(r1), "=r"(r2), "=r"(r3) : "r"(a));
}
__device__ __forceinline__ void mma16816(float& d0, float& d1, float& d2, float& d3,
                                         uint32_t a0, uint32_t a1, uint32_t a2, uint32_t a3,
                                         uint32_t b0, uint32_t b1,
                                         float c0, float c1, float c2, float c3) {
    asm volatile("mma.sync.aligned.m16n8k16.row.col.f32.f16.f16.f32 "
                 "{%0,%1,%2,%3},{%4,%5,%6,%7},{%8,%9},{%10,%11,%12,%13};"
                 : "=f"(d0), "=f"(d1), "=f"(d2), "=f"(d3)
                 : "r"(a0), "r"(a1), "r"(a2), "r"(a3), "r"(b0), "r"(b1),
                   "f"(c0), "f"(c1), "f"(c2), "f"(c3));
}
#define CP_ASYNC_16(dst, src) \
    asm volatile("cp.async.cg.shared.global [%0], [%1], 16;" :: "r"(dst), "l"(src))
#define CP_COMMIT()  asm volatile("cp.async.commit_group;")
#define CP_WAIT_ALL() asm volatile("cp.async.wait_group 0;")

__global__ void __launch_bounds__(256, 1)
mla_v5_kernel(const float* __restrict__ q,     // [T,H,D]
              const int*   __restrict__ topk,  // [T,TOPK]
              const float* __restrict__ sink,  // [H]
              float*       __restrict__ out)   // [T,H,DV]
{
    extern __shared__ char smem_raw[];
    half*  sKVh  = (half*)smem_raw;                 // [2][KVBUF]
    half*  sP    = sKVh + 2 * KVBUF;                // [32][40]
    float* sPart = (float*)(sP + HB * PSTRIDE);     // [8][32][4]
    float* sLp   = sPart + 8 * 32 * 4;              // [4][32]
    int*   sIdx  = (int*)(sLp + 128);               // [2][32]

    const int hblk = blockIdx.x;       // 0..1
    const int tok  = blockIdx.y;       // 0..511
    const int tid  = threadIdx.x;
    const int lt   = tid & 31;
    const int w    = tid >> 5;
    const int wrb  = w >> 2;           // head rowblock: 16 heads
    const int nt   = (w >> 1) & 1;     // token half: 16 tokens
    const int ks   = w & 1;            // k-split half: 288 dims

    const uint32_t skv0 = (uint32_t)__cvta_generic_to_shared(sKVh);
    const uint32_t spb  = (uint32_t)__cvta_generic_to_shared(sP);

    // ---- stage Q (pre-scaled) into sKV buf0 — coalesced ----
    {
        int h = tid >> 3, j = tid & 7;
        const float4* qs = (const float4*)(q + ((size_t)tok * HH + hblk * HB + h) * DD) + j;
        half* qd = sKVh + h * KSTRIDE;
        #pragma unroll
        for (int i = 0; i < 18; ++i) {
            float4 v = qs[i * 8];
            half2 h0 = __floats2half2_rn(v.x * SCALE_F, v.y * SCALE_F);
            half2 h1 = __floats2half2_rn(v.z * SCALE_F, v.w * SCALE_F);
            uint2 u; u.x = *(uint32_t*)&h0; u.y = *(uint32_t*)&h1;
            *(uint2*)(qd + j * 4 + i * 32) = u;
        }
    }
    __syncthreads();

    uint32_t qf[72];
    {
        uint32_t qa = skv0 + (uint32_t)(((wrb * 16 + (lt & 15)) * KSTRIDE + ks * 288 + (lt >> 4) * 8) * 2);
        #pragma unroll
        for (int s = 0; s < 18; ++s) {
            ldsm_x4(qf[4*s], qf[4*s+1], qf[4*s+2], qf[4*s+3], qa);
            qa += 32;
        }
    }
    __syncthreads();   // Q frags read before gather overwrites buf0

    const int* tkp = topk + (size_t)tok * TOPK;
    const int grow = tid >> 3;         // gather row (8 lanes / row)
    const int gcol = tid & 7;          // 16B column

    // ---- gather tile 0 into buf0 via cp.async (dst stride 128 B = src stride) ----
    {
        int raw = tkp[grow];
        if (gcol == 0) sIdx[grow] = raw;
        int r2 = raw < 0 ? 0 : raw;
        const half* src = g_kvh + (size_t)r2 * DD + gcol * 8;
        uint32_t dst = skv0 + (uint32_t)((grow * KSTRIDE + gcol * 8) * 2);
        #pragma unroll
        for (int i = 0; i < 9; ++i) CP_ASYNC_16(dst + i * 128, src + i * 64);
        CP_COMMIT();
        CP_WAIT_ALL();
    }
    __syncthreads();

    float accO[2][8][4];
    #pragma unroll
    for (int m = 0; m < 2; ++m)
        #pragma unroll
        for (int n = 0; n < 8; ++n)
            accO[m][n][0] = accO[m][n][1] = accO[m][n][2] = accO[m][n][3] = 0.0f;

    float rs0 = 0.0f, rs1 = 0.0f;      // running row-sums for this warp's token slice

    const uint32_t qkB_off = (uint32_t)(((nt * 16 + (lt & 15)) * KSTRIDE + ks * 288 + (lt >> 4) * 8) * 2);
    const uint32_t pvB_off = (uint32_t)((lt * KSTRIDE + w * 64) * 2);   // x4t: token row = lane
    const int rowa = wrb * 16 + (lt >> 2);

    for (int kt = 0; kt < NTILES; ++kt) {
        const int cur = kt & 1;
        const uint32_t kvb = skv0 + (uint32_t)(cur * (KVBUF * 2));
        const bool hasNext = (kt + 1 < NTILES);

        // ---- issue next-tile gather (cp.async, hides under whole tile body) ----
        if (hasNext) {
            int raw = tkp[(kt + 1) * TILE + grow];
            if (gcol == 0) sIdx[(cur ^ 1) * 32 + grow] = raw;
            int r2 = raw < 0 ? 0 : raw;
            const half* src = g_kvh + (size_t)r2 * DD + gcol * 8;
            uint32_t dst = skv0 + (uint32_t)((((cur ^ 1) * KVBUF) + grow * KSTRIDE + gcol * 8) * 2);
            #pragma unroll
            for (int i = 0; i < 9; ++i) CP_ASYNC_16(dst + i * 128, src + i * 64);
            CP_COMMIT();
        }

        // ---- QK: warp tile [16h x 16t], 18 k-steps, A in registers ----
        float c00 = 0.f, c01 = 0.f, c02 = 0.f, c03 = 0.f;
        float c10 = 0.f, c11 = 0.f, c12 = 0.f, c13 = 0.f;
        {
            uint32_t ka = kvb + qkB_off;
            #pragma unroll
            for (int s = 0; s < 18; ++s) {
                uint32_t b0, b1, b2, b3;
                ldsm_x4(b0, b1, b2, b3, ka); ka += 32;
                mma16816(c00, c01, c02, c03, qf[4*s], qf[4*s+1], qf[4*s+2], qf[4*s+3],
                         b0, b2, c00, c01, c02, c03);
                mma16816(c10, c11, c12, c13, qf[4*s], qf[4*s+1], qf[4*s+2], qf[4*s+3],
                         b1, b3, c10, c11, c12, c13);
            }
        }

        // export the token-half the PARTNER owns (4 floats), keep own half
        {
            float4 ex = ks ? make_float4(c00, c01, c02, c03)
                           : make_float4(c10, c11, c12, c13);
            *(float4*)(sPart + (w ^ 1) * 128 + lt * 4) = ex;
        }
        __syncthreads();   // B1: partials visible

        // ---- balanced softmax (fixed base 0): every warp exps 16h x 8t ----
        {
            float4 pp = *(const float4*)(sPart + w * 128 + lt * 4);
            float s0, s1, s2, s3;
            if (ks == 0) { s0 = c00 + pp.x; s1 = c01 + pp.y; s2 = c02 + pp.z; s3 = c03 + pp.w; }
            else         { s0 = c10 + pp.x; s1 = c11 + pp.y; s2 = c12 + pp.z; s3 = c13 + pp.w; }
            int t0 = nt * 16 + ks * 8 + (lt & 3) * 2;
            int i0 = sIdx[cur * 32 + t0];
            int i1 = sIdx[cur * 32 + t0 + 1];
            float p0 = (i0 < 0) ? 0.f : __expf(s0);
            float p1 = (i1 < 0) ? 0.f : __expf(s1);
            float p2 = (i0 < 0) ? 0.f : __expf(s2);
            float p3 = (i1 < 0) ? 0.f : __expf(s3);
            rs0 += p0 + p1;
            rs1 += p2 + p3;
            *(half2*)(sP + rowa * PSTRIDE + t0)       = __floats2half2_rn(p0, p1);
            *(half2*)(sP + (rowa + 8) * PSTRIDE + t0) = __floats2half2_rn(p2, p3);
        }
        __syncthreads();   // B2: P visible

        // ---- PV: warp tile [32h x 64d] = P[32x32] @ V[32x64], x4t loads ----
        {
            uint32_t ap[2][2][4];
            #pragma unroll
            for (int mi = 0; mi < 2; ++mi)
                #pragma unroll
                for (int k2 = 0; k2 < 2; ++k2) {
                    uint32_t aa = spb + (uint32_t)(((mi * 16 + (lt & 15)) * PSTRIDE + k2 * 16 + (lt >> 4) * 8) * 2);
                    ldsm_x4(ap[mi][k2][0], ap[mi][k2][1], ap[mi][k2][2], ap[mi][k2][3], aa);
                }
            uint32_t bbase = kvb + pvB_off;
            #pragma unroll
            for (int n2 = 0; n2 < 8; ++n2) {
                uint32_t b0, b1, b2, b3;
                ldsm_x4t(b0, b1, b2, b3, bbase + (uint32_t)(n2 * 16));
                #pragma unroll
                for (int mi = 0; mi < 2; ++mi)
                    mma16816(accO[mi][n2][0], accO[mi][n2][1], accO[mi][n2][2], accO[mi][n2][3],
                             ap[mi][0][0], ap[mi][0][1], ap[mi][0][2], ap[mi][0][3], b0, b1,
                             accO[mi][n2][0], accO[mi][n2][1], accO[mi][n2][2], accO[mi][n2][3]);
                #pragma unroll
                for (int mi = 0; mi < 2; ++mi)
                    mma16816(accO[mi][n2][0], accO[mi][n2][1], accO[mi][n2][2], accO[mi][n2][3],
                             ap[mi][1][0], ap[mi][1][1], ap[mi][1][2], ap[mi][1][3], b2, b3,
                             accO[mi][n2][0], accO[mi][n2][1], accO[mi][n2][2], accO[mi][n2][3]);
            }
        }

        CP_WAIT_ALL();     // next KV tile landed
        __syncthreads();   // B3: everyone past PV/sP; next tile readable
    }

    // ---- epilogue: export per-warp row sums, sink-aware normalize, write out ----
    {
        rs0 += __shfl_xor_sync(0xffffffffu, rs0, 1);
        rs0 += __shfl_xor_sync(0xffffffffu, rs0, 2);
        rs1 += __shfl_xor_sync(0xffffffffu, rs1, 1);
        rs1 += __shfl_xor_sync(0xffffffffu, rs1, 2);
        if ((lt & 3) == 0) {
            int slot = nt * 2 + ks;
            sLp[slot * 32 + rowa]     = rs0;
            sLp[slot * 32 + rowa + 8] = rs1;
        }
    }
    __syncthreads();

    {
        float* ob = out + ((size_t)tok * HH + hblk * HB) * DV;
        #pragma unroll
        for (int mi = 0; mi < 2; ++mi) {
            int r0 = mi * 16 + (lt >> 2);
            int r1 = r0 + 8;
            float d0 = sLp[r0] + sLp[32 + r0] + sLp[64 + r0] + sLp[96 + r0]
                     + __expf(sink[hblk * HB + r0]);
            float d1 = sLp[r1] + sLp[32 + r1] + sLp[64 + r1] + sLp[96 + r1]
                     + __expf(sink[hblk * HB + r1]);
            float rc0 = 1.0f / d0;
            float rc1 = 1.0f / d1;
            #pragma unroll
            for (int n2 = 0; n2 < 8; ++n2) {
                int d = w * 64 + n2 * 8 + (lt & 3) * 2;
                *(float2*)(ob + (size_t)r0 * DV + d) =
                    make_float2(accO[mi][n2][0] * rc0, accO[mi][n2][1] * rc0);
                *(float2*)(ob + (size_t)r1 * DV + d) =
                    make_float2(accO[mi][n2][2] * rc1, accO[mi][n2][3] * rc1);
            }
        }
    }
}

extern "C" void kernel_launch(void* const* d_in, const int* in_sizes, int n_in,
                              void* d_out, int out_size)
{
    const float* q    = (const float*)d_in[0];
    const float* kv   = (const float*)d_in[1];
    const int*   topk = (const int*)d_in[2];
    const float* sink = (const float*)d_in[3];
    float*       out  = (float*)d_out;

    // prepass: fp32 KV cache -> fp16 device-global copy
    kv_to_half_kernel<<<(NKV * DD / 4) / 256, 256>>>(kv);

    cudaFuncSetAttribute(mla_v5_kernel,
                         cudaFuncAttributeMaxDynamicSharedMemorySize, SMEM_BYTES);

    dim3 grid(HH / HB, TT);   // (2, 512)
    dim3 block(256);
    mla_v5_kernel<<<grid, block, SMEM_BYTES>>>(q, topk, sink, out);
}

// round 9
// speedup vs baseline: 11.5694x; 1.0411x over previous
#include <cuda_runtime.h>
#include <cuda_fp16.h>
#include <math.h>
#include <stdint.h>

#define TT     512
#define HH     64
#define DD     576
#define DV     512
#define NKV    8192
#define TOPK   1024
#define TILE   32
#define NTILES 32
#define HB     32
#define KSTRIDE 584               // halves per KV/Q smem row (1168 B)
#define PSTRIDE 40                // halves per P row
#define KVBUF  (TILE * KSTRIDE)   // 18688 halves
#define SCALE_F (1.0f / 24.0f)

// smem: sKV 2*KVBUF*2 | sP 32*40*2 | sPart 8*4*32*4*4 | sLp 4*32*4 | sIdx 2*32*4
#define SMEM_BYTES (2*KVBUF*2 + HB*PSTRIDE*2 + 8*4*32*4*4 + 4*32*4 + 2*32*4 + 128)

// fp16 copy of the latent cache, produced by a prepass kernel each launch
__device__ __align__(16) half g_kvh[(size_t)NKV * DD];

__global__ void __launch_bounds__(256)
kv_to_half_kernel(const float* __restrict__ kv)
{
    size_t i = (size_t)blockIdx.x * 256 + threadIdx.x;   // one float4 each
    float4 v = ((const float4*)kv)[i];
    half2 a = __floats2half2_rn(v.x, v.y);
    half2 b = __floats2half2_rn(v.z, v.w);
    uint2 u; u.x = *(uint32_t*)&a; u.y = *(uint32_t*)&b;
    ((uint2*)g_kvh)[i] = u;
}

__device__ __forceinline__ void ldsm_x4(uint32_t& r0, uint32_t& r1, uint32_t& r2, uint32_t& r3, uint32_t a) {
    asm volatile("ldmatrix.sync.aligned.m8n8.x4.shared.b16 {%0,%1,%2,%3}, [%4];"
                 : "=r"(r0), "=r"(r1), "=r"(r2), "=r"(r3) : "r"(a));
}
__device__ __forceinline__ void ldsm_x4t(uint32_t& r0, uint32_t& r1, uint32_t& r2, uint32_t& r3, uint32_t a) {
    asm volatile("ldmatrix.sync.aligned.m8n8.x4.trans.shared.b16 {%0,%1,%2,%3}, [%4];"
                 : "=r"(r0), "=r"(r1), "=r"(r2), "=r"(r3) : "r"(a));
}
__device__ __forceinline__ void mma16816(float& d0, float& d1, float& d2, float& d3,
                                         uint32_t a0, uint32_t a1, uint32_t a2, uint32_t a3,
                                         uint32_t b0, uint32_t b1,
                                         float c0, float c1, float c2, float c3) {
    asm volatile("mma.sync.aligned.m16n8k16.row.col.f32.f16.f16.f32 "
                 "{%0,%1,%2,%3},{%4,%5,%6,%7},{%8,%9},{%10,%11,%12,%13};"
                 : "=f"(d0), "=f"(d1), "=f"(d2), "=f"(d3)
                 : "r"(a0), "r"(a1), "r"(a2), "r"(a3), "r"(b0), "r"(b1),
                   "f"(c0), "f"(c1), "f"(c2), "f"(c3));
}
#define CP_ASYNC_16(dst, src) \
    asm volatile("cp.async.cg.shared.global [%0], [%1], 16;" :: "r"(dst), "l"(src))
#define CP_COMMIT()  asm volatile("cp.async.commit_group;")
#define CP_WAIT_ALL() asm volatile("cp.async.wait_group 0;")

__global__ void __launch_bounds__(256, 2)
mla_v6_kernel(const float* __restrict__ q,     // [T,H,D]
              const int*   __restrict__ topk,  // [T,TOPK]
              const float* __restrict__ sink,  // [H]
              float*       __restrict__ out)   // [T,H,DV]
{
    extern __shared__ char smem_raw[];
    half*  sKVh  = (half*)smem_raw;                 // [2][KVBUF]
    half*  sP    = sKVh + 2 * KVBUF;                // [32][40]
    float* sPart = (float*)(sP + HB * PSTRIDE);     // [8 dst][4 src][32][4]
    float* sLp   = sPart + 8 * 4 * 32 * 4;          // [4][32]
    int*   sIdx  = (int*)(sLp + 4 * 32);            // [2][32]

    const int hblk = blockIdx.x;       // 0..1
    const int tok  = blockIdx.y;       // 0..511
    const int tid  = threadIdx.x;
    const int lt   = tid & 31;
    const int w    = tid >> 5;
    const int wrb  = w >> 2;           // head rowblock: 16 heads
    const int ks   = w & 3;            // k-split quarter: 144 dims; also owns token n-tile ks

    const uint32_t skv0 = (uint32_t)__cvta_generic_to_shared(sKVh);
    const uint32_t spb  = (uint32_t)__cvta_generic_to_shared(sP);

    // ---- stage Q (pre-scaled) into sKV buf0 — coalesced ----
    {
        int h = tid >> 3, j = tid & 7;
        const float4* qs = (const float4*)(q + ((size_t)tok * HH + hblk * HB + h) * DD) + j;
        half* qd = sKVh + h * KSTRIDE;
        #pragma unroll
        for (int i = 0; i < 18; ++i) {
            float4 v = qs[i * 8];
            half2 h0 = __floats2half2_rn(v.x * SCALE_F, v.y * SCALE_F);
            half2 h1 = __floats2half2_rn(v.z * SCALE_F, v.w * SCALE_F);
            uint2 u; u.x = *(uint32_t*)&h0; u.y = *(uint32_t*)&h1;
            *(uint2*)(qd + j * 4 + i * 32) = u;
        }
    }
    __syncthreads();

    // Q A-fragments for this warp's 144-dim slice: 9 k-steps
    uint32_t qf[36];
    {
        uint32_t qa = skv0 + (uint32_t)(((wrb * 16 + (lt & 15)) * KSTRIDE + ks * 144 + (lt >> 4) * 8) * 2);
        #pragma unroll
        for (int s = 0; s < 9; ++s) {
            ldsm_x4(qf[4*s], qf[4*s+1], qf[4*s+2], qf[4*s+3], qa);
            qa += 32;
        }
    }
    __syncthreads();   // Q frags read before gather overwrites buf0

    const int* tkp = topk + (size_t)tok * TOPK;
    const int grow = tid >> 3;         // gather row (8 lanes / row)
    const int gcol = tid & 7;          // 16B column

    // ---- gather tile 0 into buf0 via cp.async ----
    {
        int raw = tkp[grow];
        if (gcol == 0) sIdx[grow] = raw;
        int r2 = raw < 0 ? 0 : raw;
        const half* src = g_kvh + (size_t)r2 * DD + gcol * 8;
        uint32_t dst = skv0 + (uint32_t)((grow * KSTRIDE + gcol * 8) * 2);
        #pragma unroll
        for (int i = 0; i < 9; ++i) CP_ASYNC_16(dst + i * 128, src + i * 64);
        CP_COMMIT();
        CP_WAIT_ALL();
    }
    __syncthreads();

    float accO[2][8][4];
    #pragma unroll
    for (int m = 0; m < 2; ++m)
        #pragma unroll
        for (int n = 0; n < 8; ++n)
            accO[m][n][0] = accO[m][n][1] = accO[m][n][2] = accO[m][n][3] = 0.0f;

    float rs0 = 0.0f, rs1 = 0.0f;      // running row-sums for this warp's token quadrant

    const uint32_t qkB_off = (uint32_t)(((lt & 15) * KSTRIDE + ks * 144 + (lt >> 4) * 8) * 2);
    const uint32_t pvB_off = (uint32_t)((lt * KSTRIDE + w * 64) * 2);   // x4t: token row = lane
    const int rowa = wrb * 16 + (lt >> 2);

    for (int kt = 0; kt < NTILES; ++kt) {
        const int cur = kt & 1;
        const uint32_t kvb = skv0 + (uint32_t)(cur * (KVBUF * 2));
        const bool hasNext = (kt + 1 < NTILES);

        // ---- issue next-tile gather (cp.async, hides under whole tile body) ----
        if (hasNext) {
            int raw = tkp[(kt + 1) * TILE + grow];
            if (gcol == 0) sIdx[(cur ^ 1) * 32 + grow] = raw;
            int r2 = raw < 0 ? 0 : raw;
            const half* src = g_kvh + (size_t)r2 * DD + gcol * 8;
            uint32_t dst = skv0 + (uint32_t)((((cur ^ 1) * KVBUF) + grow * KSTRIDE + gcol * 8) * 2);
            #pragma unroll
            for (int i = 0; i < 9; ++i) CP_ASYNC_16(dst + i * 128, src + i * 64);
            CP_COMMIT();
        }

        // ---- QK: warp tile [16h x 32t] over 144 dims (9 k-steps), A in registers ----
        float c[4][4];
        #pragma unroll
        for (int j = 0; j < 4; ++j) c[j][0] = c[j][1] = c[j][2] = c[j][3] = 0.0f;
        {
            uint32_t ka0 = kvb + qkB_off;                       // tokens 0-15
            uint32_t ka1 = ka0 + (uint32_t)(16 * KSTRIDE * 2);  // tokens 16-31
            #pragma unroll
            for (int s = 0; s < 9; ++s) {
                uint32_t b0, b1, b2, b3;
                ldsm_x4(b0, b1, b2, b3, ka0); ka0 += 32;
                mma16816(c[0][0], c[0][1], c[0][2], c[0][3],
                         qf[4*s], qf[4*s+1], qf[4*s+2], qf[4*s+3], b0, b2,
                         c[0][0], c[0][1], c[0][2], c[0][3]);
                mma16816(c[1][0], c[1][1], c[1][2], c[1][3],
                         qf[4*s], qf[4*s+1], qf[4*s+2], qf[4*s+3], b1, b3,
                         c[1][0], c[1][1], c[1][2], c[1][3]);
                ldsm_x4(b0, b1, b2, b3, ka1); ka1 += 32;
                mma16816(c[2][0], c[2][1], c[2][2], c[2][3],
                         qf[4*s], qf[4*s+1], qf[4*s+2], qf[4*s+3], b0, b2,
                         c[2][0], c[2][1], c[2][2], c[2][3]);
                mma16816(c[3][0], c[3][1], c[3][2], c[3][3],
                         qf[4*s], qf[4*s+1], qf[4*s+2], qf[4*s+3], b1, b3,
                         c[3][0], c[3][1], c[3][2], c[3][3]);
            }
        }

        // export the 3 token n-tiles owned by partner warps (same wrb)
        #pragma unroll
        for (int j = 0; j < 4; ++j) {
            if (j != ks) {
                float* pb = sPart + (((wrb * 4 + j) * 4 + ks) * 32 + lt) * 4;
                *(float4*)pb = make_float4(c[j][0], c[j][1], c[j][2], c[j][3]);
            }
        }
        __syncthreads();   // B1: partials visible

        // ---- softmax (fixed base 0) on own n-tile: sum 3 partner partials, mask, exp ----
        {
            float s0 = c[ks][0], s1 = c[ks][1], s2 = c[ks][2], s3 = c[ks][3];
            #pragma unroll
            for (int src = 0; src < 4; ++src) {
                if (src != ks) {
                    float4 pp = *(const float4*)(sPart + ((w * 4 + src) * 32 + lt) * 4);
                    s0 += pp.x; s1 += pp.y; s2 += pp.z; s3 += pp.w;
                }
            }
            int t0 = ks * 8 + (lt & 3) * 2;
            int i0 = sIdx[cur * 32 + t0];
            int i1 = sIdx[cur * 32 + t0 + 1];
            float p0 = (i0 < 0) ? 0.f : __expf(s0);
            float p1 = (i1 < 0) ? 0.f : __expf(s1);
            float p2 = (i0 < 0) ? 0.f : __expf(s2);
            float p3 = (i1 < 0) ? 0.f : __expf(s3);
            rs0 += p0 + p1;
            rs1 += p2 + p3;
            *(half2*)(sP + rowa * PSTRIDE + t0)       = __floats2half2_rn(p0, p1);
            *(half2*)(sP + (rowa + 8) * PSTRIDE + t0) = __floats2half2_rn(p2, p3);
        }
        __syncthreads();   // B2: P visible

        // ---- PV: warp tile [32h x 64d] = P[32x32] @ V[32x64], x4t loads ----
        {
            uint32_t ap[2][2][4];
            #pragma unroll
            for (int mi = 0; mi < 2; ++mi)
                #pragma unroll
                for (int k2 = 0; k2 < 2; ++k2) {
                    uint32_t aa = spb + (uint32_t)(((mi * 16 + (lt & 15)) * PSTRIDE + k2 * 16 + (lt >> 4) * 8) * 2);
                    ldsm_x4(ap[mi][k2][0], ap[mi][k2][1], ap[mi][k2][2], ap[mi][k2][3], aa);
                }
            uint32_t bbase = kvb + pvB_off;
            #pragma unroll
            for (int n2 = 0; n2 < 8; ++n2) {
                uint32_t b0, b1, b2, b3;
                ldsm_x4t(b0, b1, b2, b3, bbase + (uint32_t)(n2 * 16));
                #pragma unroll
                for (int mi = 0; mi < 2; ++mi)
                    mma16816(accO[mi][n2][0], accO[mi][n2][1], accO[mi][n2][2], accO[mi][n2][3],
                             ap[mi][0][0], ap[mi][0][1], ap[mi][0][2], ap[mi][0][3], b0, b1,
                             accO[mi][n2][0], accO[mi][n2][1], accO[mi][n2][2], accO[mi][n2][3]);
                #pragma unroll
                for (int mi = 0; mi < 2; ++mi)
                    mma16816(accO[mi][n2][0], accO[mi][n2][1], accO[mi][n2][2], accO[mi][n2][3],
                             ap[mi][1][0], ap[mi][1][1], ap[mi][1][2], ap[mi][1][3], b2, b3,
                             accO[mi][n2][0], accO[mi][n2][1], accO[mi][n2][2], accO[mi][n2][3]);
            }
        }

        CP_WAIT_ALL();     // next KV tile landed
        __syncthreads();   // B3: everyone past PV/sP; next tile readable
    }

    // ---- epilogue: export per-warp row sums (token quadrant = slot ks) ----
    {
        rs0 += __shfl_xor_sync(0xffffffffu, rs0, 1);
        rs0 += __shfl_xor_sync(0xffffffffu, rs0, 2);
        rs1 += __shfl_xor_sync(0xffffffffu, rs1, 1);
        rs1 += __shfl_xor_sync(0xffffffffu, rs1, 2);
        if ((lt & 3) == 0) {
            sLp[ks * 32 + rowa]     = rs0;
            sLp[ks * 32 + rowa + 8] = rs1;
        }
    }
    __syncthreads();

    {
        float* ob = out + ((size_t)tok * HH + hblk * HB) * DV;
        #pragma unroll
        for (int mi = 0; mi < 2; ++mi) {
            int r0 = mi * 16 + (lt >> 2);
            int r1 = r0 + 8;
            float d0 = sLp[r0] + sLp[32 + r0] + sLp[64 + r0] + sLp[96 + r0]
                     + __expf(sink[hblk * HB + r0]);
            float d1 = sLp[r1] + sLp[32 + r1] + sLp[64 + r1] + sLp[96 + r1]
                     + __expf(sink[hblk * HB + r1]);
            float rc0 = 1.0f / d0;
            float rc1 = 1.0f / d1;
            #pragma unroll
            for (int n2 = 0; n2 < 8; ++n2) {
                int d = w * 64 + n2 * 8 + (lt & 3) * 2;
                *(float2*)(ob + (size_t)r0 * DV + d) =
                    make_float2(accO[mi][n2][0] * rc0, accO[mi][n2][1] * rc0);
                *(float2*)(ob + (size_t)r1 * DV + d) =
                    make_float2(accO[mi][n2][2] * rc1, accO[mi][n2][3] * rc1);
            }
        }
    }
}

extern "C" void kernel_launch(void* const* d_in, const int* in_sizes, int n_in,
                              void* d_out, int out_size)
{
    const float* q    = (const float*)d_in[0];
    const float* kv   = (const float*)d_in[1];
    const int*   topk = (const int*)d_in[2];
    const float* sink = (const float*)d_in[3];
    float*       out  = (float*)d_out;

    // prepass: fp32 KV cache -> fp16 device-global copy
    kv_to_half_kernel<<<(NKV * DD / 4) / 256, 256>>>(kv);

    cudaFuncSetAttribute(mla_v6_kernel,
                         cudaFuncAttributeMaxDynamicSharedMemorySize, SMEM_BYTES);

    dim3 grid(HH / HB, TT);   // (2, 512)
    dim3 block(256);
    mla_v6_kernel<<<grid, block, SMEM_BYTES>>>(q, topk, sink, out);
}

// round 10
// speedup vs baseline: 11.5824x; 1.0011x over previous
#include <cuda_runtime.h>
#include <cuda_fp16.h>
#include <math.h>
#include <stdint.h>

#define TT     512
#define HH     64
#define DD     576
#define DV     512
#define NKV    8192
#define TOPK   1024
#define TILE   32
#define NTILES 32
#define HB     32
#define KSTRIDE 584               // halves per KV/Q smem row (1168 B)
#define PSTRIDE 40                // halves per P row
#define KVBUF  (TILE * KSTRIDE)   // 18688 halves
#define SCALE_F (1.0f / 24.0f)

// smem: sKV 2*KVBUF*2 | sP 32*40*2 | sPart 8*4*32*4*4 | sLp 4*32*4 | sIdx 2*32*4
#define SMEM_BYTES (2*KVBUF*2 + HB*PSTRIDE*2 + 8*4*32*4*4 + 4*32*4 + 2*32*4 + 128)

// fp16 copy of the latent cache, produced by a prepass kernel each launch
__device__ __align__(16) half g_kvh[(size_t)NKV * DD];

__global__ void __launch_bounds__(256)
kv_to_half_kernel(const float* __restrict__ kv)
{
    size_t i = (size_t)blockIdx.x * 256 + threadIdx.x;   // one float4 each
    float4 v = ((const float4*)kv)[i];
    half2 a = __floats2half2_rn(v.x, v.y);
    half2 b = __floats2half2_rn(v.z, v.w);
    uint2 u; u.x = *(uint32_t*)&a; u.y = *(uint32_t*)&b;
    ((uint2*)g_kvh)[i] = u;
}

__device__ __forceinline__ void ldsm_x4(uint32_t& r0, uint32_t& r1, uint32_t& r2, uint32_t& r3, uint32_t a) {
    asm volatile("ldmatrix.sync.aligned.m8n8.x4.shared.b16 {%0,%1,%2,%3}, [%4];"
                 : "=r"(r0), "=r"(r1), "=r"(r2), "=r"(r3) : "r"(a));
}
__device__ __forceinline__ void ldsm_x4t(uint32_t& r0, uint32_t& r1, uint32_t& r2, uint32_t& r3, uint32_t a) {
    asm volatile("ldmatrix.sync.aligned.m8n8.x4.trans.shared.b16 {%0,%1,%2,%3}, [%4];"
                 : "=r"(r0), "=r"(r1), "=r"(r2), "=r"(r3) : "r"(a));
}
__device__ __forceinline__ void mma16816(float& d0, float& d1, float& d2, float& d3,
                                         uint32_t a0, uint32_t a1, uint32_t a2, uint32_t a3,
                                         uint32_t b0, uint32_t b1,
                                         float c0, float c1, float c2, float c3) {
    asm volatile("mma.sync.aligned.m16n8k16.row.col.f32.f16.f16.f32 "
                 "{%0,%1,%2,%3},{%4,%5,%6,%7},{%8,%9},{%10,%11,%12,%13};"
                 : "=f"(d0), "=f"(d1), "=f"(d2), "=f"(d3)
                 : "r"(a0), "r"(a1), "r"(a2), "r"(a3), "r"(b0), "r"(b1),
                   "f"(c0), "f"(c1), "f"(c2), "f"(c3));
}
#define CP_ASYNC_16(dst, src) \
    asm volatile("cp.async.cg.shared.global [%0], [%1], 16;" :: "r"(dst), "l"(src))
#define CP_COMMIT()  asm volatile("cp.async.commit_group;")
#define CP_WAIT_ALL() asm volatile("cp.async.wait_group 0;")

__global__ void __launch_bounds__(256, 2)
mla_v6_kernel(const float* __restrict__ q,     // [T,H,D]
              const int*   __restrict__ topk,  // [T,TOPK]
              const float* __restrict__ sink,  // [H]
              float*       __restrict__ out)   // [T,H,DV]
{
    extern __shared__ char smem_raw[];
    half*  sKVh  = (half*)smem_raw;                 // [2][KVBUF]
    half*  sP    = sKVh + 2 * KVBUF;                // [32][40]
    float* sPart = (float*)(sP + HB * PSTRIDE);     // [8 dst][4 src][32][4]
    float* sLp   = sPart + 8 * 4 * 32 * 4;          // [4][32]
    int*   sIdx  = (int*)(sLp + 4 * 32);            // [2][32]

    const int hblk = blockIdx.x;       // 0..1
    const int tok  = blockIdx.y;       // 0..511
    const int tid  = threadIdx.x;
    const int lt   = tid & 31;
    const int w    = tid >> 5;
    const int wrb  = w >> 2;           // head rowblock: 16 heads
    const int ks   = w & 3;            // k-split quarter: 144 dims; also owns token n-tile ks

    const uint32_t skv0 = (uint32_t)__cvta_generic_to_shared(sKVh);
    const uint32_t spb  = (uint32_t)__cvta_generic_to_shared(sP);

    // ---- stage Q (pre-scaled) into sKV buf0 — coalesced ----
    {
        int h = tid >> 3, j = tid & 7;
        const float4* qs = (const float4*)(q + ((size_t)tok * HH + hblk * HB + h) * DD) + j;
        half* qd = sKVh + h * KSTRIDE;
        #pragma unroll
        for (int i = 0; i < 18; ++i) {
            float4 v = qs[i * 8];
            half2 h0 = __floats2half2_rn(v.x * SCALE_F, v.y * SCALE_F);
            half2 h1 = __floats2half2_rn(v.z * SCALE_F, v.w * SCALE_F);
            uint2 u; u.x = *(uint32_t*)&h0; u.y = *(uint32_t*)&h1;
            *(uint2*)(qd + j * 4 + i * 32) = u;
        }
    }
    __syncthreads();

    // Q A-fragments for this warp's 144-dim slice: 9 k-steps
    uint32_t qf[36];
    {
        uint32_t qa = skv0 + (uint32_t)(((wrb * 16 + (lt & 15)) * KSTRIDE + ks * 144 + (lt >> 4) * 8) * 2);
        #pragma unroll
        for (int s = 0; s < 9; ++s) {
            ldsm_x4(qf[4*s], qf[4*s+1], qf[4*s+2], qf[4*s+3], qa);
            qa += 32;
        }
    }
    __syncthreads();   // Q frags read before gather overwrites buf0

    const int* tkp = topk + (size_t)tok * TOPK;
    const int grow = tid >> 3;         // gather row (8 lanes / row)
    const int gcol = tid & 7;          // 16B column

    // ---- gather tile 0 into buf0 via cp.async ----
    {
        int raw = tkp[grow];
        if (gcol == 0) sIdx[grow] = raw;
        int r2 = raw < 0 ? 0 : raw;
        const half* src = g_kvh + (size_t)r2 * DD + gcol * 8;
        uint32_t dst = skv0 + (uint32_t)((grow * KSTRIDE + gcol * 8) * 2);
        #pragma unroll
        for (int i = 0; i < 9; ++i) CP_ASYNC_16(dst + i * 128, src + i * 64);
        CP_COMMIT();
        CP_WAIT_ALL();
    }
    __syncthreads();

    float accO[2][8][4];
    #pragma unroll
    for (int m = 0; m < 2; ++m)
        #pragma unroll
        for (int n = 0; n < 8; ++n)
            accO[m][n][0] = accO[m][n][1] = accO[m][n][2] = accO[m][n][3] = 0.0f;

    float rs0 = 0.0f, rs1 = 0.0f;      // running row-sums for this warp's token quadrant

    const uint32_t qkB_off = (uint32_t)(((lt & 15) * KSTRIDE + ks * 144 + (lt >> 4) * 8) * 2);
    const uint32_t pvB_off = (uint32_t)((lt * KSTRIDE + w * 64) * 2);   // x4t: token row = lane
    const int rowa = wrb * 16 + (lt >> 2);

    for (int kt = 0; kt < NTILES; ++kt) {
        const int cur = kt & 1;
        const uint32_t kvb = skv0 + (uint32_t)(cur * (KVBUF * 2));
        const bool hasNext = (kt + 1 < NTILES);

        // ---- issue next-tile gather (cp.async, hides under whole tile body) ----
        if (hasNext) {
            int raw = tkp[(kt + 1) * TILE + grow];
            if (gcol == 0) sIdx[(cur ^ 1) * 32 + grow] = raw;
            int r2 = raw < 0 ? 0 : raw;
            const half* src = g_kvh + (size_t)r2 * DD + gcol * 8;
            uint32_t dst = skv0 + (uint32_t)((((cur ^ 1) * KVBUF) + grow * KSTRIDE + gcol * 8) * 2);
            #pragma unroll
            for (int i = 0; i < 9; ++i) CP_ASYNC_16(dst + i * 128, src + i * 64);
            CP_COMMIT();
        }

        // ---- QK: warp tile [16h x 32t] over 144 dims (9 k-steps), A in registers ----
        float c[4][4];
        #pragma unroll
        for (int j = 0; j < 4; ++j) c[j][0] = c[j][1] = c[j][2] = c[j][3] = 0.0f;
        {
            uint32_t ka0 = kvb + qkB_off;                       // tokens 0-15
            uint32_t ka1 = ka0 + (uint32_t)(16 * KSTRIDE * 2);  // tokens 16-31
            #pragma unroll
            for (int s = 0; s < 9; ++s) {
                uint32_t b0, b1, b2, b3;
                ldsm_x4(b0, b1, b2, b3, ka0); ka0 += 32;
                mma16816(c[0][0], c[0][1], c[0][2], c[0][3],
                         qf[4*s], qf[4*s+1], qf[4*s+2], qf[4*s+3], b0, b2,
                         c[0][0], c[0][1], c[0][2], c[0][3]);
                mma16816(c[1][0], c[1][1], c[1][2], c[1][3],
                         qf[4*s], qf[4*s+1], qf[4*s+2], qf[4*s+3], b1, b3,
                         c[1][0], c[1][1], c[1][2], c[1][3]);
                ldsm_x4(b0, b1, b2, b3, ka1); ka1 += 32;
                mma16816(c[2][0], c[2][1], c[2][2], c[2][3],
                         qf[4*s], qf[4*s+1], qf[4*s+2], qf[4*s+3], b0, b2,
                         c[2][0], c[2][1], c[2][2], c[2][3]);
                mma16816(c[3][0], c[3][1], c[3][2], c[3][3],
                         qf[4*s], qf[4*s+1], qf[4*s+2], qf[4*s+3], b1, b3,
                         c[3][0], c[3][1], c[3][2], c[3][3]);
            }
        }

        // export the 3 token n-tiles owned by partner warps (same wrb)
        #pragma unroll
        for (int j = 0; j < 4; ++j) {
            if (j != ks) {
                float* pb = sPart + (((wrb * 4 + j) * 4 + ks) * 32 + lt) * 4;
                *(float4*)pb = make_float4(c[j][0], c[j][1], c[j][2], c[j][3]);
            }
        }
        __syncthreads();   // B1: partials visible

        // ---- softmax (fixed base 0) on own n-tile: sum 3 partner partials, mask, exp ----
        {
            float s0 = c[ks][0], s1 = c[ks][1], s2 = c[ks][2], s3 = c[ks][3];
            #pragma unroll
            for (int src = 0; src < 4; ++src) {
                if (src != ks) {
                    float4 pp = *(const float4*)(sPart + ((w * 4 + src) * 32 + lt) * 4);
                    s0 += pp.x; s1 += pp.y; s2 += pp.z; s3 += pp.w;
                }
            }
            int t0 = ks * 8 + (lt & 3) * 2;
            int i0 = sIdx[cur * 32 + t0];
            int i1 = sIdx[cur * 32 + t0 + 1];
            float p0 = (i0 < 0) ? 0.f : __expf(s0);
            float p1 = (i1 < 0) ? 0.f : __expf(s1);
            float p2 = (i0 < 0) ? 0.f : __expf(s2);
            float p3 = (i1 < 0) ? 0.f : __expf(s3);
            rs0 += p0 + p1;
            rs1 += p2 + p3;
            *(half2*)(sP + rowa * PSTRIDE + t0)       = __floats2half2_rn(p0, p1);
            *(half2*)(sP + (rowa + 8) * PSTRIDE + t0) = __floats2half2_rn(p2, p3);
        }
        __syncthreads();   // B2: P visible

        // ---- PV: warp tile [32h x 64d] = P[32x32] @ V[32x64], x4t loads ----
        {
            uint32_t ap[2][2][4];
            #pragma unroll
            for (int mi = 0; mi < 2; ++mi)
                #pragma unroll
                for (int k2 = 0; k2 < 2; ++k2) {
                    uint32_t aa = spb + (uint32_t)(((mi * 16 + (lt & 15)) * PSTRIDE + k2 * 16 + (lt >> 4) * 8) * 2);
                    ldsm_x4(ap[mi][k2][0], ap[mi][k2][1], ap[mi][k2][2], ap[mi][k2][3], aa);
                }
            uint32_t bbase = kvb + pvB_off;
            #pragma unroll
            for (int n2 = 0; n2 < 8; ++n2) {
                uint32_t b0, b1, b2, b3;
                ldsm_x4t(b0, b1, b2, b3, bbase + (uint32_t)(n2 * 16));
                #pragma unroll
                for (int mi = 0; mi < 2; ++mi)
                    mma16816(accO[mi][n2][0], accO[mi][n2][1], accO[mi][n2][2], accO[mi][n2][3],
                             ap[mi][0][0], ap[mi][0][1], ap[mi][0][2], ap[mi][0][3], b0, b1,
                             accO[mi][n2][0], accO[mi][n2][1], accO[mi][n2][2], accO[mi][n2][3]);
                #pragma unroll
                for (int mi = 0; mi < 2; ++mi)
                    mma16816(accO[mi][n2][0], accO[mi][n2][1], accO[mi][n2][2], accO[mi][n2][3],
                             ap[mi][1][0], ap[mi][1][1], ap[mi][1][2], ap[mi][1][3], b2, b3,
                             accO[mi][n2][0], accO[mi][n2][1], accO[mi][n2][2], accO[mi][n2][3]);
            }
        }

        CP_WAIT_ALL();     // next KV tile landed
        __syncthreads();   // B3: everyone past PV/sP; next tile readable
    }

    // ---- epilogue: export per-warp row sums (token quadrant = slot ks) ----
    {
        rs0 += __shfl_xor_sync(0xffffffffu, rs0, 1);
        rs0 += __shfl_xor_sync(0xffffffffu, rs0, 2);
        rs1 += __shfl_xor_sync(0xffffffffu, rs1, 1);
        rs1 += __shfl_xor_sync(0xffffffffu, rs1, 2);
        if ((lt & 3) == 0) {
            sLp[ks * 32 + rowa]     = rs0;
            sLp[ks * 32 + rowa + 8] = rs1;
        }
    }
    __syncthreads();

    {
        float* ob = out + ((size_t)tok * HH + hblk * HB) * DV;
        #pragma unroll
        for (int mi = 0; mi < 2; ++mi) {
            int r0 = mi * 16 + (lt >> 2);
            int r1 = r0 + 8;
            float d0 = sLp[r0] + sLp[32 + r0] + sLp[64 + r0] + sLp[96 + r0]
                     + __expf(sink[hblk * HB + r0]);
            float d1 = sLp[r1] + sLp[32 + r1] + sLp[64 + r1] + sLp[96 + r1]
                     + __expf(sink[hblk * HB + r1]);
            float rc0 = 1.0f / d0;
            float rc1 = 1.0f / d1;
            #pragma unroll
            for (int n2 = 0; n2 < 8; ++n2) {
                int d = w * 64 + n2 * 8 + (lt & 3) * 2;
                *(float2*)(ob + (size_t)r0 * DV + d) =
                    make_float2(accO[mi][n2][0] * rc0, accO[mi][n2][1] * rc0);
                *(float2*)(ob + (size_t)r1 * DV + d) =
                    make_float2(accO[mi][n2][2] * rc1, accO[mi][n2][3] * rc1);
            }
        }
    }
}

extern "C" void kernel_launch(void* const* d_in, const int* in_sizes, int n_in,
                              void* d_out, int out_size)
{
    const float* q    = (const float*)d_in[0];
    const float* kv   = (const float*)d_in[1];
    const int*   topk = (const int*)d_in[2];
    const float* sink = (const float*)d_in[3];
    float*       out  = (float*)d_out;

    // prepass: fp32 KV cache -> fp16 device-global copy
    kv_to_half_kernel<<<(NKV * DD / 4) / 256, 256>>>(kv);

    cudaFuncSetAttribute(mla_v6_kernel,
                         cudaFuncAttributeMaxDynamicSharedMemorySize, SMEM_BYTES);

    dim3 grid(HH / HB, TT);   // (2, 512)
    dim3 block(256);
    mla_v6_kernel<<<grid, block, SMEM_BYTES>>>(q, topk, sink, out);
}

// round 12
// speedup vs baseline: 11.5843x; 1.0002x over previous
#include <cuda_runtime.h>
#include <cuda_fp16.h>
#include <math.h>
#include <stdint.h>

#define TT     512
#define HH     64
#define DD     576
#define DV     512
#define NKV    8192
#define TOPK   1024
#define TILE   32
#define NTILES 32
#define HB     32
#define KSTRIDE 584               // halves per KV/Q smem row (1168 B)
#define ROWB   (KSTRIDE * 2)      // 1168 bytes
#define CPROW  1152               // bytes actually copied per KV row
#define PSTRIDE 40
#define KVBUF  (TILE * KSTRIDE)   // halves per buffer
#define SCALE_F (1.0f / 24.0f)
#define TILE_TX (TILE * CPROW)    // 36864 bytes per tile

// smem: sKV 2*KVBUF*2 | sP 32*40*2 | sPart 8*4*32*4*4 | sLp 4*32*4 | sIdx 2*32*4 | mbar 2*8
#define SP_OFFB    (2 * KVBUF * 2)
#define SPART_OFFB (SP_OFFB + HB * PSTRIDE * 2)
#define SLP_OFFB   (SPART_OFFB + 8 * 4 * 32 * 4 * 4)
#define SIDX_OFFB  (SLP_OFFB + 4 * 32 * 4)
#define SMB_OFFB   (SIDX_OFFB + 2 * 32 * 4)
#define SMEM_BYTES (SMB_OFFB + 64)

__device__ __align__(16) half g_kvh[(size_t)NKV * DD];

__global__ void __launch_bounds__(256)
kv_to_half_kernel(const float* __restrict__ kv)
{
    size_t i = (size_t)blockIdx.x * 256 + threadIdx.x;
    float4 v = ((const float4*)kv)[i];
    half2 a = __floats2half2_rn(v.x, v.y);
    half2 b = __floats2half2_rn(v.z, v.w);
    uint2 u; u.x = *(uint32_t*)&a; u.y = *(uint32_t*)&b;
    ((uint2*)g_kvh)[i] = u;
}

__device__ __forceinline__ void ldsm_x4(uint32_t& r0, uint32_t& r1, uint32_t& r2, uint32_t& r3, uint32_t a) {
    asm volatile("ldmatrix.sync.aligned.m8n8.x4.shared.b16 {%0,%1,%2,%3}, [%4];"
                 : "=r"(r0), "=r"(r1), "=r"(r2), "=r"(r3) : "r"(a));
}
__device__ __forceinline__ void ldsm_x4t(uint32_t& r0, uint32_t& r1, uint32_t& r2, uint32_t& r3, uint32_t a) {
    asm volatile("ldmatrix.sync.aligned.m8n8.x4.trans.shared.b16 {%0,%1,%2,%3}, [%4];"
                 : "=r"(r0), "=r"(r1), "=r"(r2), "=r"(r3) : "r"(a));
}
__device__ __forceinline__ void mma16816(float& d0, float& d1, float& d2, float& d3,
                                         uint32_t a0, uint32_t a1, uint32_t a2, uint32_t a3,
                                         uint32_t b0, uint32_t b1,
                                         float c0, float c1, float c2, float c3) {
    asm volatile("mma.sync.aligned.m16n8k16.row.col.f32.f16.f16.f32 "
                 "{%0,%1,%2,%3},{%4,%5,%6,%7},{%8,%9},{%10,%11,%12,%13};"
                 : "=f"(d0), "=f"(d1), "=f"(d2), "=f"(d3)
                 : "r"(a0), "r"(a1), "r"(a2), "r"(a3), "r"(b0), "r"(b1),
                   "f"(c0), "f"(c1), "f"(c2), "f"(c3));
}
#define MB_WAIT(mb, ph) do { \
    asm volatile("{\n .reg .pred P1;\n WL%=:\n" \
        " mbarrier.try_wait.parity.acquire.cta.shared::cta.b64 P1, [%0], %1, 0x989680;\n" \
        " @P1 bra.uni WD%=;\n bra.uni WL%=;\n WD%=:\n}" :: "r"(mb), "r"(ph) : "memory"); \
} while (0)

__global__ void __launch_bounds__(256, 2)
mla_v8_kernel(const float* __restrict__ q,     // [T,H,D]
              const int*   __restrict__ topk,  // [T,TOPK]
              const float* __restrict__ sink,  // [H]
              float*       __restrict__ out)   // [T,H,DV]
{
    extern __shared__ char smem_raw[];
    half*  sKVh  = (half*)smem_raw;                       // [2][KVBUF]
    half*  sP    = (half*)(smem_raw + SP_OFFB);           // [32][40]
    float* sPart = (float*)(smem_raw + SPART_OFFB);       // [8 dst][4 src][32][4]
    float* sLp   = (float*)(smem_raw + SLP_OFFB);         // [4][32]
    int*   sIdx  = (int*)(smem_raw + SIDX_OFFB);          // [2][32]

    const int hblk = blockIdx.x;       // 0..1
    const int tok  = blockIdx.y;       // 0..511
    const int tid  = threadIdx.x;
    const int lt   = tid & 31;
    const int w    = tid >> 5;
    const int wrb  = w >> 2;           // head rowblock: 16 heads
    const int ks   = w & 3;            // k-split quarter (144 dims) + owns token n-tile ks

    const uint32_t skv0 = (uint32_t)__cvta_generic_to_shared(sKVh);
    const uint32_t spb  = (uint32_t)__cvta_generic_to_shared(sP);
    const uint32_t mbar = skv0 + SMB_OFFB;                // 2 mbarriers (8B each)

    if (tid < 2) {
        asm volatile("mbarrier.init.shared.b64 [%0], 1;" :: "r"(mbar + tid * 8) : "memory");
    }

    // ---- stage Q (pre-scaled) into sKV buf0 — coalesced ----
    {
        int h = tid >> 3, j = tid & 7;
        const float4* qs = (const float4*)(q + ((size_t)tok * HH + hblk * HB + h) * DD) + j;
        half* qd = sKVh + h * KSTRIDE;
        #pragma unroll
        for (int i = 0; i < 18; ++i) {
            float4 v = qs[i * 8];
            half2 h0 = __floats2half2_rn(v.x * SCALE_F, v.y * SCALE_F);
            half2 h1 = __floats2half2_rn(v.z * SCALE_F, v.w * SCALE_F);
            uint2 u; u.x = *(uint32_t*)&h0; u.y = *(uint32_t*)&h1;
            *(uint2*)(qd + j * 4 + i * 32) = u;
        }
    }
    __syncthreads();

    // Q A-fragments for this warp's 144-dim slice: 9 k-steps
    uint32_t qf[36];
    {
        uint32_t qa = skv0 + (uint32_t)(((wrb * 16 + (lt & 15)) * KSTRIDE + ks * 144 + (lt >> 4) * 8) * 2);
        #pragma unroll
        for (int s = 0; s < 9; ++s) {
            ldsm_x4(qf[4*s], qf[4*s+1], qf[4*s+2], qf[4*s+3], qa);
            qa += 32;
        }
    }
    __syncthreads();   // Q frags read before gather overwrites buf0

    const int* tkp = topk + (size_t)tok * TOPK;

    // ---- bulk gather: warp 0, one row per lane ----
    auto gather = [&](int tile) {
        int buf = tile & 1;
        int raw = tkp[tile * TILE + lt];
        sIdx[buf * 32 + lt] = raw;
        int r2 = raw < 0 ? 0 : raw;
        if (lt == 0) {
            asm volatile("mbarrier.arrive.expect_tx.shared.b64 _, [%0], %1;"
                         :: "r"(mbar + buf * 8), "r"((uint32_t)TILE_TX) : "memory");
        }
        __syncwarp();
        uint32_t dst = skv0 + (uint32_t)(buf * (KVBUF * 2) + lt * ROWB);
        const half* src = g_kvh + (size_t)r2 * DD;
        asm volatile("cp.async.bulk.shared::cta.global.mbarrier::complete_tx::bytes [%0], [%1], %2, [%3];"
                     :: "r"(dst), "l"(src), "r"((uint32_t)CPROW), "r"(mbar + buf * 8) : "memory");
    };

    // prologue: gather tile 0, wait, sync
    if (w == 0) gather(0);
    MB_WAIT(mbar, 0);
    __syncthreads();

    float accO[2][8][4];
    #pragma unroll
    for (int m = 0; m < 2; ++m)
        #pragma unroll
        for (int n = 0; n < 8; ++n)
            accO[m][n][0] = accO[m][n][1] = accO[m][n][2] = accO[m][n][3] = 0.0f;

    float rs0 = 0.0f, rs1 = 0.0f;

    const uint32_t qkB_off = (uint32_t)(((lt & 15) * KSTRIDE + ks * 144 + (lt >> 4) * 8) * 2);
    const uint32_t pvB_off = (uint32_t)((lt * KSTRIDE + w * 64) * 2);
    const int rowa = wrb * 16 + (lt >> 2);

    for (int kt = 0; kt < NTILES; ++kt) {
        const int cur = kt & 1;
        const uint32_t kvb = skv0 + (uint32_t)(cur * (KVBUF * 2));
        const bool hasNext = (kt + 1 < NTILES);

        // ---- issue next-tile bulk gather (warp 0 only; latency hides under tile body) ----
        if (hasNext && w == 0) gather(kt + 1);

        // ---- QK: warp tile [16h x 32t] over 144 dims (9 k-steps), A in registers ----
        float c[4][4];
        #pragma unroll
        for (int j = 0; j < 4; ++j) c[j][0] = c[j][1] = c[j][2] = c[j][3] = 0.0f;
        {
            uint32_t ka0 = kvb + qkB_off;
            uint32_t ka1 = ka0 + (uint32_t)(16 * KSTRIDE * 2);
            #pragma unroll
            for (int s = 0; s < 9; ++s) {
                uint32_t b0, b1, b2, b3;
                ldsm_x4(b0, b1, b2, b3, ka0); ka0 += 32;
                mma16816(c[0][0], c[0][1], c[0][2], c[0][3],
                         qf[4*s], qf[4*s+1], qf[4*s+2], qf[4*s+3], b0, b2,
                         c[0][0], c[0][1], c[0][2], c[0][3]);
                mma16816(c[1][0], c[1][1], c[1][2], c[1][3],
                         qf[4*s], qf[4*s+1], qf[4*s+2], qf[4*s+3], b1, b3,
                         c[1][0], c[1][1], c[1][2], c[1][3]);
                ldsm_x4(b0, b1, b2, b3, ka1); ka1 += 32;
                mma16816(c[2][0], c[2][1], c[2][2], c[2][3],
                         qf[4*s], qf[4*s+1], qf[4*s+2], qf[4*s+3], b0, b2,
                         c[2][0], c[2][1], c[2][2], c[2][3]);
                mma16816(c[3][0], c[3][1], c[3][2], c[3][3],
                         qf[4*s], qf[4*s+1], qf[4*s+2], qf[4*s+3], b1, b3,
                         c[3][0], c[3][1], c[3][2], c[3][3]);
            }
        }

        // export the 3 token n-tiles owned by partner warps (same wrb)
        #pragma unroll
        for (int j = 0; j < 4; ++j) {
            if (j != ks) {
                float* pb = sPart + (((wrb * 4 + j) * 4 + ks) * 32 + lt) * 4;
                *(float4*)pb = make_float4(c[j][0], c[j][1], c[j][2], c[j][3]);
            }
        }
        __syncthreads();   // B1: partials visible

        // ---- softmax (fixed base 0) on own n-tile ----
        {
            float s0 = c[ks][0], s1 = c[ks][1], s2 = c[ks][2], s3 = c[ks][3];
            #pragma unroll
            for (int src = 0; src < 4; ++src) {
                if (src != ks) {
                    float4 pp = *(const float4*)(sPart + ((w * 4 + src) * 32 + lt) * 4);
                    s0 += pp.x; s1 += pp.y; s2 += pp.z; s3 += pp.w;
                }
            }
            int t0 = ks * 8 + (lt & 3) * 2;
            int i0 = sIdx[cur * 32 + t0];
            int i1 = sIdx[cur * 32 + t0 + 1];
            float p0 = (i0 < 0) ? 0.f : __expf(s0);
            float p1 = (i1 < 0) ? 0.f : __expf(s1);
            float p2 = (i0 < 0) ? 0.f : __expf(s2);
            float p3 = (i1 < 0) ? 0.f : __expf(s3);
            rs0 += p0 + p1;
            rs1 += p2 + p3;
            *(half2*)(sP + rowa * PSTRIDE + t0)       = __floats2half2_rn(p0, p1);
            *(half2*)(sP + (rowa + 8) * PSTRIDE + t0) = __floats2half2_rn(p2, p3);
        }
        __syncthreads();   // B2: P visible

        // ---- PV: warp tile [32h x 64d] = P[32x32] @ V[32x64] ----
        {
            uint32_t ap[2][2][4];
            #pragma unroll
            for (int mi = 0; mi < 2; ++mi)
                #pragma unroll
                for (int k2 = 0; k2 < 2; ++k2) {
                    uint32_t aa = spb + (uint32_t)(((mi * 16 + (lt & 15)) * PSTRIDE + k2 * 16 + (lt >> 4) * 8) * 2);
                    ldsm_x4(ap[mi][k2][0], ap[mi][k2][1], ap[mi][k2][2], ap[mi][k2][3], aa);
                }
            uint32_t bbase = kvb + pvB_off;
            #pragma unroll
            for (int n2 = 0; n2 < 8; ++n2) {
                uint32_t b0, b1, b2, b3;
                ldsm_x4t(b0, b1, b2, b3, bbase + (uint32_t)(n2 * 16));
                #pragma unroll
                for (int mi = 0; mi < 2; ++mi)
                    mma16816(accO[mi][n2][0], accO[mi][n2][1], accO[mi][n2][2], accO[mi][n2][3],
                             ap[mi][0][0], ap[mi][0][1], ap[mi][0][2], ap[mi][0][3], b0, b1,
                             accO[mi][n2][0], accO[mi][n2][1], accO[mi][n2][2], accO[mi][n2][3]);
                #pragma unroll
                for (int mi = 0; mi < 2; ++mi)
                    mma16816(accO[mi][n2][0], accO[mi][n2][1], accO[mi][n2][2], accO[mi][n2][3],
                             ap[mi][1][0], ap[mi][1][1], ap[mi][1][2], ap[mi][1][3], b2, b3,
                             accO[mi][n2][0], accO[mi][n2][1], accO[mi][n2][2], accO[mi][n2][3]);
            }
        }

        // next tile's KV must be visible before anyone reads it next iteration
        if (hasNext) MB_WAIT(mbar + (((kt + 1) & 1) * 8), ((kt + 1) >> 1) & 1);
        __syncthreads();   // B3: PV done, sP/sPart reusable, gathered tile visible to all
    }

    // ---- epilogue ----
    {
        rs0 += __shfl_xor_sync(0xffffffffu, rs0, 1);
        rs0 += __shfl_xor_sync(0xffffffffu, rs0, 2);
        rs1 += __shfl_xor_sync(0xffffffffu, rs1, 1);
        rs1 += __shfl_xor_sync(0xffffffffu, rs1, 2);
        if ((lt & 3) == 0) {
            sLp[ks * 32 + rowa]     = rs0;
            sLp[ks * 32 + rowa + 8] = rs1;
        }
    }
    __syncthreads();

    {
        float* ob = out + ((size_t)tok * HH + hblk * HB) * DV;
        #pragma unroll
        for (int mi = 0; mi < 2; ++mi) {
            int r0 = mi * 16 + (lt >> 2);
            int r1 = r0 + 8;
            float d0 = sLp[r0] + sLp[32 + r0] + sLp[64 + r0] + sLp[96 + r0]
                     + __expf(sink[hblk * HB + r0]);
            float d1 = sLp[r1] + sLp[32 + r1] + sLp[64 + r1] + sLp[96 + r1]
                     + __expf(sink[hblk * HB + r1]);
            float rc0 = 1.0f / d0;
            float rc1 = 1.0f / d1;
            #pragma unroll
            for (int n2 = 0; n2 < 8; ++n2) {
                int d = w * 64 + n2 * 8 + (lt & 3) * 2;
                *(float2*)(ob + (size_t)r0 * DV + d) =
                    make_float2(accO[mi][n2][0] * rc0, accO[mi][n2][1] * rc0);
                *(float2*)(ob + (size_t)r1 * DV + d) =
                    make_float2(accO[mi][n2][2] * rc1, accO[mi][n2][3] * rc1);
            }
        }
    }
}

extern "C" void kernel_launch(void* const* d_in, const int* in_sizes, int n_in,
                              void* d_out, int out_size)
{
    const float* q    = (const float*)d_in[0];
    const float* kv   = (const float*)d_in[1];
    const int*   topk = (const int*)d_in[2];
    const float* sink = (const float*)d_in[3];
    float*       out  = (float*)d_out;

    kv_to_half_kernel<<<(NKV * DD / 4) / 256, 256>>>(kv);

    cudaFuncSetAttribute(mla_v8_kernel,
                         cudaFuncAttributeMaxDynamicSharedMemorySize, SMEM_BYTES);

    dim3 grid(HH / HB, TT);   // (2, 512)
    dim3 block(256);
    mla_v8_kernel<<<grid, block, SMEM_BYTES>>>(q, topk, sink, out);
}